// round 4
// baseline (speedup 1.0000x reference)
#include <cuda_runtime.h>
#include <math.h>

#define NB 4
#define CIN 3
#define NC 64
#define H0 256
#define W0 256
#define NPIX0 (H0*W0)
#define HP 264
#define NP (HP*HP)      /* 69696 */
#define NR 64           /* kept ky modes: 0..31 and 232..263 */
#define NM 32           /* kept kx modes */
#define SPW (64*64*32*32)
#define INV_HP (1.0f/264.0f)

// ---------------- scratch (device globals; no runtime allocation) ----------
__device__ float  g_x  [NB*NC*NP];
__device__ float  g_hbr[NB*NC*NP];
__device__ float2 g_T1 [NB*NC*NR*HP];
__device__ float2 g_xf [NB*NC*NR*NM];
__device__ float2 g_of [NB*NC*NR*NM];
__device__ float2 g_U  [NB*NC*HP*NM];
__device__ float2 g_Fy [NR*HP];     // (cos, -sin) for kept ky rows, [r][y]
__device__ float2 g_Fx [NM*HP];     // (cos, -sin), [k][x]
__device__ float2 g_FxT[HP*NM];     // transposed [x][k]
__device__ float  g_FyC[HP*40];     // cos, [y][mode], stride 40 (modes 0..32 used)
__device__ float  g_FyS[HP*40];     // sin
__device__ float  g_W1T[3*64*64];   // [L][k][o]
__device__ float  g_W2T[3*64*128];  // [L][k][o]
__device__ float  g_W3T[3*128*64];  // [L][k][o]

__device__ __forceinline__ float gelu_exact(float v) {
    return 0.5f * v * (1.0f + erff(v * 0.70710678118654752440f));
}

// ---------------- init ------------------------------------------------------
__global__ void k_tables() {
    int idx = blockIdx.x * 256 + threadIdx.x;
    if (idx < NR*HP) {
        int r = idx / HP, y = idx % HP;
        int ky = (r < 32) ? r : r + 200;           // 232..263
        int m = (ky * y) % HP;
        double a = 6.283185307179586 * (double)m / (double)HP;
        g_Fy[idx] = make_float2((float)cos(a), (float)(-sin(a)));
    } else if (idx < NR*HP + NM*HP) {
        int j = idx - NR*HP;
        int k = j / HP, xx = j % HP;
        int m = (k * xx) % HP;
        double a = 6.283185307179586 * (double)m / (double)HP;
        float2 f = make_float2((float)cos(a), (float)(-sin(a)));
        g_Fx[j] = f;
        g_FxT[xx*NM + k] = f;
    } else if (idx < NR*HP + NM*HP + HP*33) {
        int j = idx - NR*HP - NM*HP;
        int y = j / 33, m = j % 33;
        int mm = (m * y) % HP;
        double a = 6.283185307179586 * (double)mm / (double)HP;
        g_FyC[y*40 + m] = (float)cos(a);
        g_FyS[y*40 + m] = (float)sin(a);
    }
}

// transpose weights: W*T[L][k][o] = W[L][o][k]
__global__ void k_wprep(const float* __restrict__ cw,
                        const float* __restrict__ m1w,
                        const float* __restrict__ m2w) {
    int idx = blockIdx.x * 256 + threadIdx.x;
    if (idx < 12288) {                       // 3 x 64x64
        int L = idx / 4096, r = idx % 4096, o = r / 64, k = r % 64;
        g_W1T[L*4096 + k*64 + o] = cw[idx];
    } else if (idx < 12288 + 24576) {        // 3 x 128x64
        int i = idx - 12288;
        int L = i / 8192, r = i % 8192, o = r / 64, k = r % 64;
        g_W2T[L*8192 + k*128 + o] = m1w[i];
    } else if (idx < 12288 + 49152) {        // 3 x 64x128
        int i = idx - 12288 - 24576;
        int L = i / 8192, r = i % 8192, o = r / 128, k = r % 128;
        g_W3T[L*8192 + k*64 + o] = m2w[i];
    }
}

__global__ void k_zero_x() {
    int n = NB*NC*NP;
    for (int i = blockIdx.x * 256 + threadIdx.x; i < n; i += gridDim.x * 256)
        g_x[i] = 0.0f;
}

// ---------------- lift: 5 -> 32 (GELU) -> 64 -------------------------------
__global__ void __launch_bounds__(256) k_lift(
    const float* __restrict__ x,
    const float* __restrict__ w1, const float* __restrict__ b1,
    const float* __restrict__ w2, const float* __restrict__ b2)
{
    __shared__ float sw1[32*5], sb1[32], sw2[64*32], sb2[64];
    for (int i = threadIdx.x; i < 160;  i += 256) sw1[i] = w1[i];
    for (int i = threadIdx.x; i < 32;   i += 256) sb1[i] = b1[i];
    for (int i = threadIdx.x; i < 2048; i += 256) sw2[i] = w2[i];
    for (int i = threadIdx.x; i < 64;   i += 256) sb2[i] = b2[i];
    __syncthreads();
    int b = blockIdx.y;
    int p = blockIdx.x * 256 + threadIdx.x;
    int i = p >> 8, j = p & 255;
    float f[5];
    f[0] = x[(b*CIN + 0)*NPIX0 + p];
    f[1] = x[(b*CIN + 1)*NPIX0 + p];
    f[2] = x[(b*CIN + 2)*NPIX0 + p];
    f[3] = (float)i * (1.0f/255.0f);
    f[4] = (float)j * (1.0f/255.0f);
    float h[32];
    #pragma unroll
    for (int c1 = 0; c1 < 32; c1++) {
        float v = sb1[c1];
        #pragma unroll
        for (int q = 0; q < 5; q++) v = fmaf(sw1[c1*5+q], f[q], v);
        h[c1] = gelu_exact(v);
    }
    int base = b*NC*NP + i*HP + j;
    for (int c2 = 0; c2 < 64; c2++) {
        float v = sb2[c2];
        #pragma unroll
        for (int c1 = 0; c1 < 32; c1++) v = fmaf(sw2[c2*32+c1], h[c1], v);
        g_x[base + c2*NP] = v;
    }
}

// ---------------- fused local branch; weights via LDG, data via LDS --------
// 128 threads, 64-px tile; micro-tile 8 rows x 4 px.
__global__ void __launch_bounds__(128) k_local(
    const float* __restrict__ in, float* __restrict__ out,
    const float* __restrict__ W1T, const float* __restrict__ B1,
    const float* __restrict__ W2T, const float* __restrict__ B2,
    const float* __restrict__ W3T, const float* __restrict__ B3)
{
    extern __shared__ __align__(16) float sm_l[];
    float* sX = sm_l;            // 64x64
    float* sY = sm_l + 4096;     // 64x64
    float* sT = sm_l + 8192;     // 128x64
    const int tid = threadIdx.x;
    const int ty = tid >> 4, tx = tid & 15;
    const int r0 = ty * 8, x0 = tx * 4;
    const int base = blockIdx.y * (NC*NP) + blockIdx.x * 64;

    #pragma unroll
    for (int i = 0; i < 32; i++) {
        int idx = tid + i*128;
        sX[idx] = in[base + (idx >> 6)*NP + (idx & 63)];
    }
    __syncthreads();

    float acc[8][4];
    // ---- stage 1: Y = W1 X + b1  (K=64)
    #pragma unroll
    for (int i = 0; i < 8; i++) {
        float bv = __ldg(&B1[r0 + i]);
        #pragma unroll
        for (int j = 0; j < 4; j++) acc[i][j] = bv;
    }
    for (int k = 0; k < 64; k++) {
        float4 a0 = __ldg((const float4*)&W1T[k*64 + r0]);
        float4 a1 = __ldg((const float4*)&W1T[k*64 + r0 + 4]);
        float4 b  = *(const float4*)&sX[k*64 + x0];
        const float av[8] = {a0.x,a0.y,a0.z,a0.w,a1.x,a1.y,a1.z,a1.w};
        const float bv[4] = {b.x,b.y,b.z,b.w};
        #pragma unroll
        for (int i = 0; i < 8; i++)
            #pragma unroll
            for (int j = 0; j < 4; j++)
                acc[i][j] = fmaf(av[i], bv[j], acc[i][j]);
    }
    #pragma unroll
    for (int i = 0; i < 8; i++)
        *(float4*)&sY[(r0+i)*64 + x0] = make_float4(acc[i][0],acc[i][1],acc[i][2],acc[i][3]);
    __syncthreads();

    // ---- stage 2: T = gelu(W2 Y + b2), 128 rows in 2 halves (K=64)
    #pragma unroll
    for (int h = 0; h < 2; h++) {
        #pragma unroll
        for (int i = 0; i < 8; i++) {
            float bv = __ldg(&B2[h*64 + r0 + i]);
            #pragma unroll
            for (int j = 0; j < 4; j++) acc[i][j] = bv;
        }
        for (int k = 0; k < 64; k++) {
            float4 a0 = __ldg((const float4*)&W2T[k*128 + h*64 + r0]);
            float4 a1 = __ldg((const float4*)&W2T[k*128 + h*64 + r0 + 4]);
            float4 b  = *(const float4*)&sY[k*64 + x0];
            const float av[8] = {a0.x,a0.y,a0.z,a0.w,a1.x,a1.y,a1.z,a1.w};
            const float bv[4] = {b.x,b.y,b.z,b.w};
            #pragma unroll
            for (int i = 0; i < 8; i++)
                #pragma unroll
                for (int j = 0; j < 4; j++)
                    acc[i][j] = fmaf(av[i], bv[j], acc[i][j]);
        }
        #pragma unroll
        for (int i = 0; i < 8; i++)
            *(float4*)&sT[(h*64 + r0 + i)*64 + x0] =
                make_float4(gelu_exact(acc[i][0]), gelu_exact(acc[i][1]),
                            gelu_exact(acc[i][2]), gelu_exact(acc[i][3]));
    }
    __syncthreads();

    // ---- stage 3: OUT = W3 T + b3 (K=128)
    #pragma unroll
    for (int i = 0; i < 8; i++) {
        float bv = __ldg(&B3[r0 + i]);
        #pragma unroll
        for (int j = 0; j < 4; j++) acc[i][j] = bv;
    }
    for (int k = 0; k < 128; k++) {
        float4 a0 = __ldg((const float4*)&W3T[k*64 + r0]);
        float4 a1 = __ldg((const float4*)&W3T[k*64 + r0 + 4]);
        float4 b  = *(const float4*)&sT[k*64 + x0];
        const float av[8] = {a0.x,a0.y,a0.z,a0.w,a1.x,a1.y,a1.z,a1.w};
        const float bv[4] = {b.x,b.y,b.z,b.w};
        #pragma unroll
        for (int i = 0; i < 8; i++)
            #pragma unroll
            for (int j = 0; j < 4; j++)
                acc[i][j] = fmaf(av[i], bv[j], acc[i][j]);
    }
    #pragma unroll
    for (int i = 0; i < 8; i++)
        *(float4*)&out[base + (r0+i)*NP + x0] =
            make_float4(acc[i][0],acc[i][1],acc[i][2],acc[i][3]);
}

// ---------------- S1: row DFT, Hermitian-halved, split cos/sin tables ------
// 264 threads: xt=tid%33 (8 px), mq=tid/33 (4 modes; group 0 also does mode 32)
__global__ void __launch_bounds__(264, 2) k_dft_rows() {
    extern __shared__ __align__(16) float twid[];   // sC[264*40] + sS[264*40]
    float* sC = twid;
    float* sS = twid + HP*40;
    const int bc = blockIdx.x;
    const int tid = threadIdx.x;
    for (int i = tid; i < HP*40; i += 264) { sC[i] = g_FyC[i]; sS[i] = g_FyS[i]; }
    __syncthreads();

    const int xt = tid % 33, mq = tid / 33;
    const int x0 = xt * 8, m0 = mq * 4;
    const float* img = g_x + bc*NP;

    float ar[4][8], as[4][8], ar32[8], as32[8];
    #pragma unroll
    for (int m = 0; m < 4; m++)
        #pragma unroll
        for (int j = 0; j < 8; j++) { ar[m][j] = 0.f; as[m][j] = 0.f; }
    #pragma unroll
    for (int j = 0; j < 8; j++) { ar32[j] = 0.f; as32[j] = 0.f; }

    for (int y = 0; y < HP; y++) {
        float4 v0 = __ldg((const float4*)(img + y*HP + x0));
        float4 v1 = __ldg((const float4*)(img + y*HP + x0 + 4));
        const float vv[8] = {v0.x,v0.y,v0.z,v0.w,v1.x,v1.y,v1.z,v1.w};
        float4 c4 = *(const float4*)&sC[y*40 + m0];
        float4 s4 = *(const float4*)&sS[y*40 + m0];
        const float cv[4] = {c4.x,c4.y,c4.z,c4.w};
        const float sv[4] = {s4.x,s4.y,s4.z,s4.w};
        #pragma unroll
        for (int m = 0; m < 4; m++)
            #pragma unroll
            for (int j = 0; j < 8; j++) {
                ar[m][j] = fmaf(vv[j], cv[m], ar[m][j]);
                as[m][j] = fmaf(vv[j], sv[m], as[m][j]);
            }
        if (mq == 0) {
            float c32 = sC[y*40 + 32], s32 = sS[y*40 + 32];
            #pragma unroll
            for (int j = 0; j < 8; j++) {
                ar32[j] = fmaf(vv[j], c32, ar32[j]);
                as32[j] = fmaf(vv[j], s32, as32[j]);
            }
        }
    }
    #pragma unroll
    for (int m = 0; m < 4; m++) {
        int mm = m0 + m;
        {   // lo row: ky = mm, value (ar, -as)
            float4* dst = (float4*)&g_T1[(bc*NR + mm)*HP + x0];
            dst[0] = make_float4(ar[m][0], -as[m][0], ar[m][1], -as[m][1]);
            dst[1] = make_float4(ar[m][2], -as[m][2], ar[m][3], -as[m][3]);
            dst[2] = make_float4(ar[m][4], -as[m][4], ar[m][5], -as[m][5]);
            dst[3] = make_float4(ar[m][6], -as[m][6], ar[m][7], -as[m][7]);
        }
        if (mm >= 1) {   // hi row: ky = 264-mm -> row 64-mm, conj
            float4* dst = (float4*)&g_T1[(bc*NR + (64 - mm))*HP + x0];
            dst[0] = make_float4(ar[m][0], as[m][0], ar[m][1], as[m][1]);
            dst[1] = make_float4(ar[m][2], as[m][2], ar[m][3], as[m][3]);
            dst[2] = make_float4(ar[m][4], as[m][4], ar[m][5], as[m][5]);
            dst[3] = make_float4(ar[m][6], as[m][6], ar[m][7], as[m][7]);
        }
    }
    if (mq == 0) {   // mode 32 -> row 32 (ky=232 = conj of ky=32)
        float4* dst = (float4*)&g_T1[(bc*NR + 32)*HP + x0];
        dst[0] = make_float4(ar32[0], as32[0], ar32[1], as32[1]);
        dst[1] = make_float4(ar32[2], as32[2], ar32[3], as32[3]);
        dst[2] = make_float4(ar32[4], as32[4], ar32[5], as32[5]);
        dst[3] = make_float4(ar32[6], as32[6], ar32[7], as32[7]);
    }
}

// ---------------- S2: col DFT; 128 thr, micro 2k x 4r, x unroll 2 ----------
__global__ void __launch_bounds__(128) k_dft_cols() {
    extern __shared__ __align__(16) float2 t1s[];   // [32][264]
    const int bc = blockIdx.x, rbase = blockIdx.y * 32;
    for (int i = threadIdx.x; i < 32*HP; i += 128) {
        int rl = i / HP, x = i % HP;
        t1s[rl*HP + x] = g_T1[(bc*NR + rbase + rl)*HP + x];
    }
    __syncthreads();
    const int kq = threadIdx.x & 15, rq = threadIdx.x >> 4;
    const int k0 = kq * 2, r0 = rq * 4;
    float accr[2][4], acci[2][4];
    #pragma unroll
    for (int a = 0; a < 2; a++)
        #pragma unroll
        for (int i = 0; i < 4; i++) { accr[a][i] = 0.f; acci[a][i] = 0.f; }
    for (int x = 0; x < HP; x += 2) {
        float4 f0 = __ldg((const float4*)&g_FxT[x*NM + k0]);       // (c,-s) k0,k0+1 @ x
        float4 f1 = __ldg((const float4*)&g_FxT[(x+1)*NM + k0]);   // @ x+1
        #pragma unroll
        for (int i = 0; i < 4; i++) {
            float4 p = *(const float4*)&t1s[(r0+i)*HP + x];        // (re,im)@x, (re,im)@x+1
            accr[0][i] = fmaf(p.x, f0.x, fmaf(-p.y, f0.y, fmaf(p.z, f1.x, fmaf(-p.w, f1.y, accr[0][i]))));
            acci[0][i] = fmaf(p.x, f0.y, fmaf( p.y, f0.x, fmaf(p.z, f1.y, fmaf( p.w, f1.x, acci[0][i]))));
            accr[1][i] = fmaf(p.x, f0.z, fmaf(-p.y, f0.w, fmaf(p.z, f1.z, fmaf(-p.w, f1.w, accr[1][i]))));
            acci[1][i] = fmaf(p.x, f0.w, fmaf( p.y, f0.z, fmaf(p.z, f1.w, fmaf( p.w, f1.z, acci[1][i]))));
        }
    }
    #pragma unroll
    for (int i = 0; i < 4; i++) {
        float4 v = make_float4(accr[0][i], acci[0][i], accr[1][i], acci[1][i]);
        *(float4*)&g_xf[(bc*NR + rbase + r0 + i)*NM + k0] = v;
    }
}

// ---------------- S3: per-mode 64x64 complex channel mix -------------------
__global__ void __launch_bounds__(256) k_chanmix(
    const float* __restrict__ w1r, const float* __restrict__ w1i,
    const float* __restrict__ w2r, const float* __restrict__ w2i)
{
    int r = blockIdx.x >> 5, k = blockIdx.x & 31;
    __shared__ float wre[NC*NC];
    __shared__ float wim[NC*NC];
    __shared__ float2 xs[NB][NC];
    const float* wr; const float* wi; int m1;
    if (r < 32) { wr = w1r; wi = w1i; m1 = r; }
    else        { wr = w2r; wi = w2i; m1 = r - 32; }
    int woff = m1*32 + k;
    for (int idx = threadIdx.x; idx < NC*NC; idx += 256) {
        wre[idx] = wr[idx*1024 + woff];
        wim[idx] = wi[idx*1024 + woff];
    }
    {
        int b = threadIdx.x >> 6, i = threadIdx.x & 63;
        xs[b][i] = g_xf[((b*NC + i)*NR + r)*NM + k];
    }
    __syncthreads();
    int o = threadIdx.x & 63, b = threadIdx.x >> 6;
    float ar = 0.f, ai = 0.f;
    #pragma unroll 4
    for (int i = 0; i < NC; i++) {
        float2 xv = xs[b][i];
        float wrv = wre[i*64 + o], wiv = wim[i*64 + o];
        ar += xv.x*wrv - xv.y*wiv;
        ai += xv.x*wiv + xv.y*wrv;
    }
    g_of[((b*NC + o)*NR + r)*NM + k] = make_float2(ar, ai);
}

// ---------------- S4: inverse DFT along ky; 8 y per thread, aligned chunks -
__global__ void __launch_bounds__(256) k_idft_rows() {
    __shared__ float2 os[NR*NM];
    const int bo = blockIdx.x;
    for (int idx = threadIdx.x; idx < NR*NM; idx += 256)
        os[idx] = g_of[bo*(NR*NM) + idx];
    __syncthreads();
    const int k = threadIdx.x & 31, yg = threadIdx.x >> 5;
    for (int it = 0; it < 5; it++) {
        if (it == 4 && yg != 0) return;
        int y0 = it*64 + yg*8;                 // it<4: 0..255 ; it=4,yg=0: 256
        float ur[8] = {0,0,0,0,0,0,0,0}, ui[8] = {0,0,0,0,0,0,0,0};
        for (int r = 0; r < NR; r++) {
            float2 o = os[r*NM + k];
            const float2* fp = &g_Fy[r*HP + y0];
            float4 fA = __ldg((const float4*)fp);
            float4 fB = __ldg((const float4*)(fp + 2));
            float4 fC = __ldg((const float4*)(fp + 4));
            float4 fD = __ldg((const float4*)(fp + 6));
            // f=(cos,-sin); inverse: ur += ox*cos - oy*sin = ox*f.x + oy*f.y
            //               ui += oy*cos + ox*sin = oy*f.x - ox*f.y
            ur[0]=fmaf(o.x,fA.x,fmaf(o.y,fA.y,ur[0])); ui[0]=fmaf(o.y,fA.x,fmaf(-o.x,fA.y,ui[0]));
            ur[1]=fmaf(o.x,fA.z,fmaf(o.y,fA.w,ur[1])); ui[1]=fmaf(o.y,fA.z,fmaf(-o.x,fA.w,ui[1]));
            ur[2]=fmaf(o.x,fB.x,fmaf(o.y,fB.y,ur[2])); ui[2]=fmaf(o.y,fB.x,fmaf(-o.x,fB.y,ui[2]));
            ur[3]=fmaf(o.x,fB.z,fmaf(o.y,fB.w,ur[3])); ui[3]=fmaf(o.y,fB.z,fmaf(-o.x,fB.w,ui[3]));
            ur[4]=fmaf(o.x,fC.x,fmaf(o.y,fC.y,ur[4])); ui[4]=fmaf(o.y,fC.x,fmaf(-o.x,fC.y,ui[4]));
            ur[5]=fmaf(o.x,fC.z,fmaf(o.y,fC.w,ur[5])); ui[5]=fmaf(o.y,fC.z,fmaf(-o.x,fC.w,ui[5]));
            ur[6]=fmaf(o.x,fD.x,fmaf(o.y,fD.y,ur[6])); ui[6]=fmaf(o.y,fD.x,fmaf(-o.x,fD.y,ui[6]));
            ur[7]=fmaf(o.x,fD.z,fmaf(o.y,fD.w,ur[7])); ui[7]=fmaf(o.y,fD.z,fmaf(-o.x,fD.w,ui[7]));
        }
        #pragma unroll
        for (int j = 0; j < 8; j++)
            g_U[(bo*HP + y0 + j)*NM + k] = make_float2(ur[j]*INV_HP, ui[j]*INV_HP);
    }
}

// ---------------- S5: real inverse along kx + add local branch (+crop) -----
// grid (11 y-tiles of 24, 256 bo); 264 thr: yq=tid%8 (3 y), xt=tid/8 (8 px)
template<bool LAST>
__global__ void __launch_bounds__(264) k_idft_cols_add(float* __restrict__ out) {
    __shared__ float2 us[24*33];
    const int bo = blockIdx.y, ybase = blockIdx.x * 24;
    const int tid = threadIdx.x;
    for (int i = tid; i < 24*NM; i += 264) {
        int yl = i >> 5, k = i & 31;
        us[yl*33 + k] = g_U[(bo*HP + ybase + yl)*NM + k];
    }
    __syncthreads();
    const int yq = tid & 7, xt = tid >> 3;   // xt 0..32
    const int x0 = xt * 8;
    float s[3][8];
    #pragma unroll
    for (int j = 0; j < 3; j++) {
        float u0 = us[(yq*3 + j)*33].x;
        #pragma unroll
        for (int p = 0; p < 8; p++) s[j][p] = u0;
    }
    for (int k = 1; k < NM; k++) {
        const float2* fp = &g_Fx[k*HP + x0];
        float4 fA = __ldg((const float4*)fp);
        float4 fB = __ldg((const float4*)(fp + 2));
        float4 fC = __ldg((const float4*)(fp + 4));
        float4 fD = __ldg((const float4*)(fp + 6));
        #pragma unroll
        for (int j = 0; j < 3; j++) {
            float2 u = us[(yq*3 + j)*33 + k];
            float ux = 2.f*u.x, uy = 2.f*u.y;
            s[j][0]=fmaf(ux,fA.x,fmaf(uy,fA.y,s[j][0])); s[j][1]=fmaf(ux,fA.z,fmaf(uy,fA.w,s[j][1]));
            s[j][2]=fmaf(ux,fB.x,fmaf(uy,fB.y,s[j][2])); s[j][3]=fmaf(ux,fB.z,fmaf(uy,fB.w,s[j][3]));
            s[j][4]=fmaf(ux,fC.x,fmaf(uy,fC.y,s[j][4])); s[j][5]=fmaf(ux,fC.z,fmaf(uy,fC.w,s[j][5]));
            s[j][6]=fmaf(ux,fD.x,fmaf(uy,fD.y,s[j][6])); s[j][7]=fmaf(ux,fD.z,fmaf(uy,fD.w,s[j][7]));
        }
    }
    #pragma unroll
    for (int j = 0; j < 3; j++) {
        int y = ybase + yq*3 + j;
        int idx = bo*NP + y*HP + x0;
        float4 h0 = *(const float4*)&g_hbr[idx];
        float4 h1 = *(const float4*)&g_hbr[idx + 4];
        float4 r0 = make_float4(h0.x + s[j][0]*INV_HP, h0.y + s[j][1]*INV_HP,
                                h0.z + s[j][2]*INV_HP, h0.w + s[j][3]*INV_HP);
        float4 r1 = make_float4(h1.x + s[j][4]*INV_HP, h1.y + s[j][5]*INV_HP,
                                h1.z + s[j][6]*INV_HP, h1.w + s[j][7]*INV_HP);
        if (LAST) {
            if (y < H0 && x0 < W0) {
                *(float4*)&out[bo*NPIX0 + y*W0 + x0]     = r0;
                *(float4*)&out[bo*NPIX0 + y*W0 + x0 + 4] = r1;
            }
        } else {
            *(float4*)&g_x[idx]     = r0;
            *(float4*)&g_x[idx + 4] = r1;
        }
    }
}

// ---------------- launch -----------------------------------------------------
extern "C" void kernel_launch(void* const* d_in, const int* in_sizes, int n_in,
                              void* d_out, int out_size)
{
    const float* x   = (const float*)d_in[0];
    const float* lw1 = (const float*)d_in[1];
    const float* lb1 = (const float*)d_in[2];
    const float* lw2 = (const float*)d_in[3];
    const float* lb2 = (const float*)d_in[4];
    const float* cw  = (const float*)d_in[5];
    const float* cb  = (const float*)d_in[6];
    const float* m1w = (const float*)d_in[7];
    const float* m1b = (const float*)d_in[8];
    const float* m2w = (const float*)d_in[9];
    const float* m2b = (const float*)d_in[10];
    const float* s1r = (const float*)d_in[11];
    const float* s1i = (const float*)d_in[12];
    const float* s2r = (const float*)d_in[13];
    const float* s2i = (const float*)d_in[14];
    float* out = (float*)d_out;

    float *px, *ph, *pw1, *pw2, *pw3;
    cudaGetSymbolAddress((void**)&px,  g_x);
    cudaGetSymbolAddress((void**)&ph,  g_hbr);
    cudaGetSymbolAddress((void**)&pw1, g_W1T);
    cudaGetSymbolAddress((void**)&pw2, g_W2T);
    cudaGetSymbolAddress((void**)&pw3, g_W3T);

    const int LOCAL_SMEM = 16384 * 4;       // 65536
    const int DFTR_SMEM  = 2 * HP * 40 * 4; // 84480
    const int DFTC_SMEM  = 32 * HP * 8;     // 67584
    cudaFuncSetAttribute(k_local,    cudaFuncAttributeMaxDynamicSharedMemorySize, LOCAL_SMEM);
    cudaFuncSetAttribute(k_dft_rows, cudaFuncAttributeMaxDynamicSharedMemorySize, DFTR_SMEM);
    cudaFuncSetAttribute(k_dft_cols, cudaFuncAttributeMaxDynamicSharedMemorySize, DFTC_SMEM);

    k_tables<<<134, 256>>>();
    k_wprep<<<240, 256>>>(cw, m1w, m2w);
    k_zero_x<<<4096, 256>>>();
    k_lift<<<dim3(256, NB), 256>>>(x, lw1, lb1, lw2, lb2);

    for (int L = 0; L < 3; L++) {
        k_local<<<dim3(NP/64, NB), 128, LOCAL_SMEM>>>(
            px, ph,
            pw1 + L*64*64,  cb  + L*64,
            pw2 + L*64*128, m1b + L*128,
            pw3 + L*128*64, m2b + L*64);
        k_dft_rows<<<NB*NC, 264, DFTR_SMEM>>>();
        k_dft_cols<<<dim3(NB*NC, 2), 128, DFTC_SMEM>>>();
        k_chanmix<<<NR*NM, 256>>>(s1r + L*SPW, s1i + L*SPW, s2r + L*SPW, s2i + L*SPW);
        k_idft_rows<<<NB*NC, 256>>>();
        if (L < 2) k_idft_cols_add<false><<<dim3(11, NB*NC), 264>>>(out);
        else       k_idft_cols_add<true ><<<dim3(11, NB*NC), 264>>>(out);
    }
}

// round 5
// speedup vs baseline: 1.4236x; 1.4236x over previous
#include <cuda_runtime.h>
#include <math.h>

#define NB 4
#define CIN 3
#define NC 64
#define H0 256
#define W0 256
#define NPIX0 (H0*W0)
#define HP 264
#define NP (HP*HP)      /* 69696 */
#define NR 64           /* kept ky modes: 0..31 and 232..263 */
#define NM 32           /* kept kx modes */
#define SPW (64*64*32*32)
#define INV_HP (1.0f/264.0f)

// ---------------- scratch (device globals; no runtime allocation) ----------
__device__ float  g_x  [NB*NC*NP];
__device__ float  g_hbr[NB*NC*NP];
__device__ float2 g_T1 [NB*NC*NR*HP];
__device__ float2 g_xf [NB*NC*NR*NM];
__device__ float2 g_of [NB*NC*NR*NM];
__device__ float2 g_Fy [NR*HP];     // (cos, -sin) for kept ky rows, [r][y]
__device__ float2 g_Fx [NM*HP];     // (cos, -sin), [k][x]
__device__ float2 g_FxT[HP*NM];     // transposed [x][k]

__device__ __forceinline__ float gelu_exact(float v) {
    return 0.5f * v * (1.0f + erff(v * 0.70710678118654752440f));
}

// ---------------- init ------------------------------------------------------
__global__ void k_tables() {
    int idx = blockIdx.x * 256 + threadIdx.x;
    if (idx < NR*HP) {
        int r = idx / HP, y = idx % HP;
        int ky = (r < 32) ? r : r + 200;           // 232..263
        int m = (ky * y) % HP;
        double a = 6.283185307179586 * (double)m / (double)HP;
        g_Fy[idx] = make_float2((float)cos(a), (float)(-sin(a)));
    } else if (idx < NR*HP + NM*HP) {
        int j = idx - NR*HP;
        int k = j / HP, xx = j % HP;
        int m = (k * xx) % HP;
        double a = 6.283185307179586 * (double)m / (double)HP;
        float2 f = make_float2((float)cos(a), (float)(-sin(a)));
        g_Fx[j] = f;
        g_FxT[xx*NM + k] = f;
    }
}

__global__ void k_zero_x() {
    int n = NB*NC*NP;
    for (int i = blockIdx.x * 256 + threadIdx.x; i < n; i += gridDim.x * 256)
        g_x[i] = 0.0f;
}

// ---------------- lift: 5 -> 32 (GELU) -> 64 -------------------------------
__global__ void __launch_bounds__(256) k_lift(
    const float* __restrict__ x,
    const float* __restrict__ w1, const float* __restrict__ b1,
    const float* __restrict__ w2, const float* __restrict__ b2)
{
    __shared__ float sw1[32*5], sb1[32], sw2[64*32], sb2[64];
    for (int i = threadIdx.x; i < 160;  i += 256) sw1[i] = w1[i];
    for (int i = threadIdx.x; i < 32;   i += 256) sb1[i] = b1[i];
    for (int i = threadIdx.x; i < 2048; i += 256) sw2[i] = w2[i];
    for (int i = threadIdx.x; i < 64;   i += 256) sb2[i] = b2[i];
    __syncthreads();
    int b = blockIdx.y;
    int p = blockIdx.x * 256 + threadIdx.x;
    int i = p >> 8, j = p & 255;
    float f[5];
    f[0] = x[(b*CIN + 0)*NPIX0 + p];
    f[1] = x[(b*CIN + 1)*NPIX0 + p];
    f[2] = x[(b*CIN + 2)*NPIX0 + p];
    f[3] = (float)i * (1.0f/255.0f);
    f[4] = (float)j * (1.0f/255.0f);
    float h[32];
    #pragma unroll
    for (int c1 = 0; c1 < 32; c1++) {
        float v = sb1[c1];
        #pragma unroll
        for (int q = 0; q < 5; q++) v = fmaf(sw1[c1*5+q], f[q], v);
        h[c1] = gelu_exact(v);
    }
    int base = b*NC*NP + i*HP + j;
    for (int c2 = 0; c2 < 64; c2++) {
        float v = sb2[c2];
        #pragma unroll
        for (int c1 = 0; c1 < 32; c1++) v = fmaf(sw2[c2*32+c1], h[c1], v);
        g_x[base + c2*NP] = v;
    }
}

// ---------------- fused local branch (round-3 proven version) --------------
__global__ void __launch_bounds__(256, 2) k_local(
    const float* __restrict__ in, float* __restrict__ out,
    const float* __restrict__ W1, const float* __restrict__ B1,
    const float* __restrict__ W2, const float* __restrict__ B2,
    const float* __restrict__ W3, const float* __restrict__ B3)
{
    extern __shared__ __align__(16) float sm_local[];
    float* sX = sm_local;           // 64x64
    float* sY = sm_local + 4096;    // 64x64
    float* sT = sm_local + 8192;    // 128x64
    float* sW = sm_local + 16384;   // up to 8704 floats
    const int tid = threadIdx.x;
    const int ty = tid >> 4, tx = tid & 15;
    const int r0 = ty * 4, x0 = tx * 4;
    const int base = blockIdx.y * (NC*NP) + blockIdx.x * 64;

    #pragma unroll
    for (int i = 0; i < 16; i++) {
        int idx = tid + i*256;
        sX[idx] = in[base + (idx >> 6)*NP + (idx & 63)];
        sW[(idx & 63)*68 + (idx >> 6)] = W1[idx];
    }
    __syncthreads();

    float acc[4][4];
    // ---- stage 1: Y = W1 X + b1
    #pragma unroll
    for (int i = 0; i < 4; i++) {
        float bv = B1[r0 + i];
        #pragma unroll
        for (int j = 0; j < 4; j++) acc[i][j] = bv;
    }
    for (int k = 0; k < 64; k++) {
        float4 a = *(const float4*)&sW[k*68 + r0];
        float4 b = *(const float4*)&sX[k*64 + x0];
        const float av[4] = {a.x, a.y, a.z, a.w};
        const float bv[4] = {b.x, b.y, b.z, b.w};
        #pragma unroll
        for (int i = 0; i < 4; i++)
            #pragma unroll
            for (int j = 0; j < 4; j++)
                acc[i][j] = fmaf(av[i], bv[j], acc[i][j]);
    }
    #pragma unroll
    for (int i = 0; i < 4; i++)
        *(float4*)&sY[(r0+i)*64 + x0] = make_float4(acc[i][0], acc[i][1], acc[i][2], acc[i][3]);
    __syncthreads();

    #pragma unroll
    for (int i = 0; i < 32; i++) {
        int idx = tid + i*256;
        sW[(idx & 63)*132 + (idx >> 6)] = W2[idx];
    }
    __syncthreads();

    // ---- stage 2: T = gelu(W2 Y + b2)
    #pragma unroll
    for (int h = 0; h < 2; h++) {
        #pragma unroll
        for (int i = 0; i < 4; i++) {
            float bv = B2[h*64 + r0 + i];
            #pragma unroll
            for (int j = 0; j < 4; j++) acc[i][j] = bv;
        }
        for (int k = 0; k < 64; k++) {
            float4 a = *(const float4*)&sW[k*132 + h*64 + r0];
            float4 b = *(const float4*)&sY[k*64 + x0];
            const float av[4] = {a.x, a.y, a.z, a.w};
            const float bv[4] = {b.x, b.y, b.z, b.w};
            #pragma unroll
            for (int i = 0; i < 4; i++)
                #pragma unroll
                for (int j = 0; j < 4; j++)
                    acc[i][j] = fmaf(av[i], bv[j], acc[i][j]);
        }
        #pragma unroll
        for (int i = 0; i < 4; i++) {
            float4 r = make_float4(gelu_exact(acc[i][0]), gelu_exact(acc[i][1]),
                                   gelu_exact(acc[i][2]), gelu_exact(acc[i][3]));
            *(float4*)&sT[(h*64 + r0 + i)*64 + x0] = r;
        }
    }
    __syncthreads();

    #pragma unroll
    for (int i = 0; i < 32; i++) {
        int idx = tid + i*256;
        sW[(idx & 127)*68 + (idx >> 7)] = W3[idx];
    }
    __syncthreads();

    // ---- stage 3: OUT = W3 T + b3 (K=128)
    #pragma unroll
    for (int i = 0; i < 4; i++) {
        float bv = B3[r0 + i];
        #pragma unroll
        for (int j = 0; j < 4; j++) acc[i][j] = bv;
    }
    for (int k = 0; k < 128; k++) {
        float4 a = *(const float4*)&sW[k*68 + r0];
        float4 b = *(const float4*)&sT[k*64 + x0];
        const float av[4] = {a.x, a.y, a.z, a.w};
        const float bv[4] = {b.x, b.y, b.z, b.w};
        #pragma unroll
        for (int i = 0; i < 4; i++)
            #pragma unroll
            for (int j = 0; j < 4; j++)
                acc[i][j] = fmaf(av[i], bv[j], acc[i][j]);
    }
    #pragma unroll
    for (int i = 0; i < 4; i++)
        *(float4*)&out[base + (r0+i)*NP + x0] =
            make_float4(acc[i][0], acc[i][1], acc[i][2], acc[i][3]);
}

// ---------------- S1: row DFT, Hermitian-halved + image prefetch -----------
__global__ void __launch_bounds__(264, 2) k_dft_rows() {
    extern __shared__ __align__(16) float2 fy_s[];   // 33 x 264
    const int bc = blockIdx.x;
    const int tid = threadIdx.x;
    for (int idx = tid; idx < 33*HP; idx += 264) {
        int m = idx / HP, y = idx % HP;
        float2 f;
        if (m < 32) f = g_Fy[m*HP + y];
        else { f = g_Fy[32*HP + y]; f.y = -f.y; }   // ky=32 = conj(ky=232)
        fy_s[idx] = f;
    }
    __syncthreads();
    const int xt = tid % 66, rq = tid / 66;
    const int x0 = xt * 4, m0 = rq * 8;
    const float* img = g_x + bc*NP;
    float ar[9][4], ai[9][4];
    #pragma unroll
    for (int r = 0; r < 9; r++)
        #pragma unroll
        for (int j = 0; j < 4; j++) { ar[r][j] = 0.f; ai[r][j] = 0.f; }

    float4 vcur = __ldg((const float4*)(img + x0));
    for (int y = 0; y < HP; y++) {
        float4 vnext = vcur;
        if (y < HP-1) vnext = __ldg((const float4*)(img + (y+1)*HP + x0));
        const float vv[4] = {vcur.x, vcur.y, vcur.z, vcur.w};
        #pragma unroll
        for (int r = 0; r < 9; r++) {
            float2 f = fy_s[(m0 + r)*HP + y];
            #pragma unroll
            for (int j = 0; j < 4; j++) {
                ar[r][j] = fmaf(vv[j], f.x, ar[r][j]);
                ai[r][j] = fmaf(vv[j], f.y, ai[r][j]);
            }
        }
        vcur = vnext;
    }
    #pragma unroll
    for (int r = 0; r < 9; r++) {
        int m = m0 + r;
        if (m <= 31) {
            float2* dst = &g_T1[(bc*NR + m)*HP + x0];
            #pragma unroll
            for (int j = 0; j < 4; j++) dst[j] = make_float2(ar[r][j], ai[r][j]);
        }
        if (m >= 1) {
            float2* dst = &g_T1[(bc*NR + (64 - m))*HP + x0];
            #pragma unroll
            for (int j = 0; j < 4; j++) dst[j] = make_float2(ar[r][j], -ai[r][j]);
        }
    }
}

// ---------------- S2: col DFT (round-3 proven version) ---------------------
__global__ void __launch_bounds__(256) k_dft_cols() {
    __shared__ float2 t1s[16*HP];
    const int bc = blockIdx.x, rg = blockIdx.y;   // 16 r per block
    for (int idx = threadIdx.x; idx < 16*HP; idx += 256)
        t1s[idx] = g_T1[(bc*NR + rg*16)*HP + idx];
    __syncthreads();
    const int k = threadIdx.x & 31, rq = threadIdx.x >> 5;
    const int r0 = rq * 2;
    float a0r = 0.f, a0i = 0.f, a1r = 0.f, a1i = 0.f;
    for (int x = 0; x < HP; x++) {
        float2 f = __ldg(&g_FxT[x*NM + k]);
        float2 p = t1s[r0*HP + x];
        float2 q = t1s[(r0+1)*HP + x];
        a0r = fmaf(p.x, f.x, fmaf(-p.y, f.y, a0r));
        a0i = fmaf(p.x, f.y, fmaf( p.y, f.x, a0i));
        a1r = fmaf(q.x, f.x, fmaf(-q.y, f.y, a1r));
        a1i = fmaf(q.x, f.y, fmaf( q.y, f.x, a1i));
    }
    int r = rg*16 + r0;
    g_xf[(bc*NR + r    )*NM + k] = make_float2(a0r, a0i);
    g_xf[(bc*NR + r + 1)*NM + k] = make_float2(a1r, a1i);
}

// ---------------- S3: per-mode 64x64 complex channel mix -------------------
__global__ void __launch_bounds__(256) k_chanmix(
    const float* __restrict__ w1r, const float* __restrict__ w1i,
    const float* __restrict__ w2r, const float* __restrict__ w2i)
{
    int r = blockIdx.x >> 5, k = blockIdx.x & 31;
    __shared__ float wre[NC*NC];
    __shared__ float wim[NC*NC];
    __shared__ float2 xs[NB][NC];
    const float* wr; const float* wi; int m1;
    if (r < 32) { wr = w1r; wi = w1i; m1 = r; }
    else        { wr = w2r; wi = w2i; m1 = r - 32; }
    int woff = m1*32 + k;
    for (int idx = threadIdx.x; idx < NC*NC; idx += 256) {
        wre[idx] = wr[idx*1024 + woff];
        wim[idx] = wi[idx*1024 + woff];
    }
    {
        int b = threadIdx.x >> 6, i = threadIdx.x & 63;
        xs[b][i] = g_xf[((b*NC + i)*NR + r)*NM + k];
    }
    __syncthreads();
    int o = threadIdx.x & 63, b = threadIdx.x >> 6;
    float ar = 0.f, ai = 0.f;
    #pragma unroll 4
    for (int i = 0; i < NC; i++) {
        float2 xv = xs[b][i];
        float wrv = wre[i*64 + o], wiv = wim[i*64 + o];
        ar += xv.x*wrv - xv.y*wiv;
        ai += xv.x*wiv + xv.y*wrv;
    }
    g_of[((b*NC + o)*NR + r)*NM + k] = make_float2(ar, ai);
}

// ---------------- fused inverse: S4 (iDFT ky) + S5 (real iDFT kx) ----------
// One block per (b,c). U kept in smem: twiddle table g_Fx read once per block.
template<bool LAST>
__global__ void __launch_bounds__(264) k_inv(float* __restrict__ out) {
    extern __shared__ __align__(16) float2 sm_inv[];
    float2* os = sm_inv;            // 64*32
    float2* Us = sm_inv + NR*NM;    // 264*32
    const int bo = blockIdx.x;
    const int tid = threadIdx.x;
    for (int idx = tid; idx < NR*NM; idx += 264)
        os[idx] = g_of[bo*(NR*NM) + idx];
    __syncthreads();

    // ---- phase A (S4): U[y,k] = (1/HP) * sum_r of[r,k] * conj(Fy[r,y])
    if (tid < 256) {
        const int k = tid & 31, yq = tid >> 5;
        for (int it = 0; it < 9; it++) {
            int yg = yq + it*8;
            if (yg >= 66) break;
            int y0 = yg * 4;
            float ar[4] = {0,0,0,0}, ai[4] = {0,0,0,0};
            for (int r = 0; r < NR; r++) {
                float2 o = os[r*NM + k];
                const float2* fp = &g_Fy[r*HP + y0];
                float4 fA = __ldg((const float4*)fp);
                float4 fB = __ldg((const float4*)(fp + 2));
                // f=(cos,-sin); inverse: ar += ox*f.x + oy*f.y ; ai += oy*f.x - ox*f.y
                ar[0] = fmaf(o.x, fA.x, fmaf(o.y, fA.y, ar[0]));
                ai[0] = fmaf(o.y, fA.x, fmaf(-o.x, fA.y, ai[0]));
                ar[1] = fmaf(o.x, fA.z, fmaf(o.y, fA.w, ar[1]));
                ai[1] = fmaf(o.y, fA.z, fmaf(-o.x, fA.w, ai[1]));
                ar[2] = fmaf(o.x, fB.x, fmaf(o.y, fB.y, ar[2]));
                ai[2] = fmaf(o.y, fB.x, fmaf(-o.x, fB.y, ai[2]));
                ar[3] = fmaf(o.x, fB.z, fmaf(o.y, fB.w, ar[3]));
                ai[3] = fmaf(o.y, fB.z, fmaf(-o.x, fB.w, ai[3]));
            }
            #pragma unroll
            for (int j = 0; j < 4; j++)
                Us[(y0 + j)*NM + k] = make_float2(ar[j]*INV_HP, ai[j]*INV_HP);
        }
    }
    __syncthreads();

    // ---- phase B (S5): out[y,x] = hbr + (1/HP)*(U[y,0].re + 2*sum_k Re(U)*cos - Im(U)*sin)
    const int xt = tid % 33, yq = tid / 33;   // 8 px, 8 y-groups
    const int x0 = xt * 8;
    for (int p = 0; p < 9; p++) {
        int ybase = p*32 + yq*4;
        if (p == 8 && yq >= 2) break;         // y 256..263 only
        float s[4][8];
        #pragma unroll
        for (int j = 0; j < 4; j++) {
            float u0 = Us[(ybase + j)*NM].x;
            #pragma unroll
            for (int q = 0; q < 8; q++) s[j][q] = u0;
        }
        for (int k = 1; k < NM; k++) {
            const float2* fp = &g_Fx[k*HP + x0];
            float4 fA = __ldg((const float4*)fp);
            float4 fB = __ldg((const float4*)(fp + 2));
            float4 fC = __ldg((const float4*)(fp + 4));
            float4 fD = __ldg((const float4*)(fp + 6));
            #pragma unroll
            for (int j = 0; j < 4; j++) {
                float2 u = Us[(ybase + j)*NM + k];
                float ux = 2.f*u.x, uy = 2.f*u.y;
                s[j][0]=fmaf(ux,fA.x,fmaf(uy,fA.y,s[j][0])); s[j][1]=fmaf(ux,fA.z,fmaf(uy,fA.w,s[j][1]));
                s[j][2]=fmaf(ux,fB.x,fmaf(uy,fB.y,s[j][2])); s[j][3]=fmaf(ux,fB.z,fmaf(uy,fB.w,s[j][3]));
                s[j][4]=fmaf(ux,fC.x,fmaf(uy,fC.y,s[j][4])); s[j][5]=fmaf(ux,fC.z,fmaf(uy,fC.w,s[j][5]));
                s[j][6]=fmaf(ux,fD.x,fmaf(uy,fD.y,s[j][6])); s[j][7]=fmaf(ux,fD.z,fmaf(uy,fD.w,s[j][7]));
            }
        }
        #pragma unroll
        for (int j = 0; j < 4; j++) {
            int y = ybase + j;
            int idx = bo*NP + y*HP + x0;
            float4 h0 = *(const float4*)&g_hbr[idx];
            float4 h1 = *(const float4*)&g_hbr[idx + 4];
            float4 r0 = make_float4(h0.x + s[j][0]*INV_HP, h0.y + s[j][1]*INV_HP,
                                    h0.z + s[j][2]*INV_HP, h0.w + s[j][3]*INV_HP);
            float4 r1 = make_float4(h1.x + s[j][4]*INV_HP, h1.y + s[j][5]*INV_HP,
                                    h1.z + s[j][6]*INV_HP, h1.w + s[j][7]*INV_HP);
            if (LAST) {
                if (y < H0 && x0 < W0) {
                    *(float4*)&out[bo*NPIX0 + y*W0 + x0]     = r0;
                    *(float4*)&out[bo*NPIX0 + y*W0 + x0 + 4] = r1;
                }
            } else {
                *(float4*)&g_x[idx]     = r0;
                *(float4*)&g_x[idx + 4] = r1;
            }
        }
    }
}

// ---------------- launch -----------------------------------------------------
extern "C" void kernel_launch(void* const* d_in, const int* in_sizes, int n_in,
                              void* d_out, int out_size)
{
    const float* x   = (const float*)d_in[0];
    const float* lw1 = (const float*)d_in[1];
    const float* lb1 = (const float*)d_in[2];
    const float* lw2 = (const float*)d_in[3];
    const float* lb2 = (const float*)d_in[4];
    const float* cw  = (const float*)d_in[5];
    const float* cb  = (const float*)d_in[6];
    const float* m1w = (const float*)d_in[7];
    const float* m1b = (const float*)d_in[8];
    const float* m2w = (const float*)d_in[9];
    const float* m2b = (const float*)d_in[10];
    const float* s1r = (const float*)d_in[11];
    const float* s1i = (const float*)d_in[12];
    const float* s2r = (const float*)d_in[13];
    const float* s2i = (const float*)d_in[14];
    float* out = (float*)d_out;

    float *px, *ph;
    cudaGetSymbolAddress((void**)&px, g_x);
    cudaGetSymbolAddress((void**)&ph, g_hbr);

    const int LOCAL_SMEM = 25088 * 4;            // 100352 B
    const int DFTR_SMEM  = 33 * HP * 8;          // 69696 B
    const int INV_SMEM   = (NR*NM + HP*NM) * 8;  // 83968 B
    cudaFuncSetAttribute(k_local,      cudaFuncAttributeMaxDynamicSharedMemorySize, LOCAL_SMEM);
    cudaFuncSetAttribute(k_dft_rows,   cudaFuncAttributeMaxDynamicSharedMemorySize, DFTR_SMEM);
    cudaFuncSetAttribute(k_inv<false>, cudaFuncAttributeMaxDynamicSharedMemorySize, INV_SMEM);
    cudaFuncSetAttribute(k_inv<true >, cudaFuncAttributeMaxDynamicSharedMemorySize, INV_SMEM);

    k_tables<<<132, 256>>>();
    k_zero_x<<<4096, 256>>>();
    k_lift<<<dim3(256, NB), 256>>>(x, lw1, lb1, lw2, lb2);

    for (int L = 0; L < 3; L++) {
        k_local<<<dim3(NP/64, NB), 256, LOCAL_SMEM>>>(
            px, ph,
            cw  + L*64*64,   cb  + L*64,
            m1w + L*128*64,  m1b + L*128,
            m2w + L*64*128,  m2b + L*64);
        k_dft_rows<<<NB*NC, 264, DFTR_SMEM>>>();
        k_dft_cols<<<dim3(NB*NC, 4), 256>>>();
        k_chanmix<<<NR*NM, 256>>>(s1r + L*SPW, s1i + L*SPW, s2r + L*SPW, s2i + L*SPW);
        if (L < 2) k_inv<false><<<NB*NC, 264, INV_SMEM>>>(out);
        else       k_inv<true ><<<NB*NC, 264, INV_SMEM>>>(out);
    }
}

// round 6
// speedup vs baseline: 1.6390x; 1.1513x over previous
#include <cuda_runtime.h>
#include <math.h>

#define NB 4
#define CIN 3
#define NC 64
#define H0 256
#define W0 256
#define NPIX0 (H0*W0)
#define HP 264
#define NP (HP*HP)      /* 69696 */
#define NR 64           /* kept ky modes: 0..31 and 232..263 */
#define NM 32           /* kept kx modes */
#define SPW (64*64*32*32)
#define INV_HP (1.0f/264.0f)

// ---------------- scratch (device globals; no runtime allocation) ----------
__device__ float  g_x  [NB*NC*NP];
__device__ float  g_hbr[NB*NC*NP];
__device__ float2 g_T1 [NB*NC*33*HP];  // row-DFT, modes 0..32 only (Hermitian)
__device__ float2 g_xf [NB*NC*NR*NM];
__device__ float2 g_of [NB*NC*NR*NM];
__device__ float2 g_Fy [NR*HP];     // (cos, -sin) for kept ky rows, [r][y]
__device__ float2 g_Fx [NM*HP];     // (cos, -sin), [k][x]
__device__ float2 g_FxT[HP*NM];     // transposed [x][k]

__device__ __forceinline__ float gelu_exact(float v) {
    return 0.5f * v * (1.0f + erff(v * 0.70710678118654752440f));
}

// ---------------- init ------------------------------------------------------
__global__ void k_tables() {
    int idx = blockIdx.x * 256 + threadIdx.x;
    if (idx < NR*HP) {
        int r = idx / HP, y = idx % HP;
        int ky = (r < 32) ? r : r + 200;           // 232..263
        int m = (ky * y) % HP;
        double a = 6.283185307179586 * (double)m / (double)HP;
        g_Fy[idx] = make_float2((float)cos(a), (float)(-sin(a)));
    } else if (idx < NR*HP + NM*HP) {
        int j = idx - NR*HP;
        int k = j / HP, xx = j % HP;
        int m = (k * xx) % HP;
        double a = 6.283185307179586 * (double)m / (double)HP;
        float2 f = make_float2((float)cos(a), (float)(-sin(a)));
        g_Fx[j] = f;
        g_FxT[xx*NM + k] = f;
    }
}

__global__ void k_zero_x() {
    int n = NB*NC*NP;
    for (int i = blockIdx.x * 256 + threadIdx.x; i < n; i += gridDim.x * 256)
        g_x[i] = 0.0f;
}

// ---------------- lift: 5 -> 32 (GELU) -> 64 -------------------------------
__global__ void __launch_bounds__(256) k_lift(
    const float* __restrict__ x,
    const float* __restrict__ w1, const float* __restrict__ b1,
    const float* __restrict__ w2, const float* __restrict__ b2)
{
    __shared__ float sw1[32*5], sb1[32], sw2[64*32], sb2[64];
    for (int i = threadIdx.x; i < 160;  i += 256) sw1[i] = w1[i];
    for (int i = threadIdx.x; i < 32;   i += 256) sb1[i] = b1[i];
    for (int i = threadIdx.x; i < 2048; i += 256) sw2[i] = w2[i];
    for (int i = threadIdx.x; i < 64;   i += 256) sb2[i] = b2[i];
    __syncthreads();
    int b = blockIdx.y;
    int p = blockIdx.x * 256 + threadIdx.x;
    int i = p >> 8, j = p & 255;
    float f[5];
    f[0] = x[(b*CIN + 0)*NPIX0 + p];
    f[1] = x[(b*CIN + 1)*NPIX0 + p];
    f[2] = x[(b*CIN + 2)*NPIX0 + p];
    f[3] = (float)i * (1.0f/255.0f);
    f[4] = (float)j * (1.0f/255.0f);
    float h[32];
    #pragma unroll
    for (int c1 = 0; c1 < 32; c1++) {
        float v = sb1[c1];
        #pragma unroll
        for (int q = 0; q < 5; q++) v = fmaf(sw1[c1*5+q], f[q], v);
        h[c1] = gelu_exact(v);
    }
    int base = b*NC*NP + i*HP + j;
    for (int c2 = 0; c2 < 64; c2++) {
        float v = sb2[c2];
        #pragma unroll
        for (int c1 = 0; c1 < 32; c1++) v = fmaf(sw2[c2*32+c1], h[c1], v);
        g_x[base + c2*NP] = v;
    }
}

// ---------------- fused local branch: 128 thr, 8x4 micro, weights in smem --
__global__ void __launch_bounds__(128, 2) k_local(
    const float* __restrict__ in, float* __restrict__ out,
    const float* __restrict__ W1, const float* __restrict__ B1,
    const float* __restrict__ W2, const float* __restrict__ B2,
    const float* __restrict__ W3, const float* __restrict__ B3)
{
    extern __shared__ __align__(16) float sm_local[];
    float* sX = sm_local;           // 64x64
    float* sY = sm_local + 4096;    // 64x64
    float* sT = sm_local + 8192;    // 128x64
    float* sW = sm_local + 16384;   // up to 8704 floats
    const int tid = threadIdx.x;
    const int ty = tid >> 4, tx = tid & 15;   // 8 x 16
    const int r0 = ty * 8, x0 = tx * 4;
    const int base = blockIdx.y * (NC*NP) + blockIdx.x * 64;

    #pragma unroll
    for (int i = 0; i < 32; i++) {
        int idx = tid + i*128;
        sX[idx] = in[base + (idx >> 6)*NP + (idx & 63)];
        sW[(idx & 63)*68 + (idx >> 6)] = W1[idx];
    }
    __syncthreads();

    float acc[8][4];
    // ---- stage 1: Y = W1 X + b1  (K=64)
    #pragma unroll
    for (int i = 0; i < 8; i++) {
        float bv = B1[r0 + i];
        #pragma unroll
        for (int j = 0; j < 4; j++) acc[i][j] = bv;
    }
    for (int k = 0; k < 64; k++) {
        float4 a0 = *(const float4*)&sW[k*68 + r0];
        float4 a1 = *(const float4*)&sW[k*68 + r0 + 4];
        float4 b  = *(const float4*)&sX[k*64 + x0];
        const float av[8] = {a0.x,a0.y,a0.z,a0.w,a1.x,a1.y,a1.z,a1.w};
        const float bv[4] = {b.x,b.y,b.z,b.w};
        #pragma unroll
        for (int i = 0; i < 8; i++)
            #pragma unroll
            for (int j = 0; j < 4; j++)
                acc[i][j] = fmaf(av[i], bv[j], acc[i][j]);
    }
    #pragma unroll
    for (int i = 0; i < 8; i++)
        *(float4*)&sY[(r0+i)*64 + x0] = make_float4(acc[i][0],acc[i][1],acc[i][2],acc[i][3]);
    __syncthreads();

    #pragma unroll
    for (int i = 0; i < 64; i++) {
        int idx = tid + i*128;
        sW[(idx & 63)*132 + (idx >> 6)] = W2[idx];
    }
    __syncthreads();

    // ---- stage 2: T = gelu(W2 Y + b2), 128 rows in 2 halves (K=64)
    #pragma unroll
    for (int h = 0; h < 2; h++) {
        #pragma unroll
        for (int i = 0; i < 8; i++) {
            float bv = B2[h*64 + r0 + i];
            #pragma unroll
            for (int j = 0; j < 4; j++) acc[i][j] = bv;
        }
        for (int k = 0; k < 64; k++) {
            float4 a0 = *(const float4*)&sW[k*132 + h*64 + r0];
            float4 a1 = *(const float4*)&sW[k*132 + h*64 + r0 + 4];
            float4 b  = *(const float4*)&sY[k*64 + x0];
            const float av[8] = {a0.x,a0.y,a0.z,a0.w,a1.x,a1.y,a1.z,a1.w};
            const float bv[4] = {b.x,b.y,b.z,b.w};
            #pragma unroll
            for (int i = 0; i < 8; i++)
                #pragma unroll
                for (int j = 0; j < 4; j++)
                    acc[i][j] = fmaf(av[i], bv[j], acc[i][j]);
        }
        #pragma unroll
        for (int i = 0; i < 8; i++)
            *(float4*)&sT[(h*64 + r0 + i)*64 + x0] =
                make_float4(gelu_exact(acc[i][0]), gelu_exact(acc[i][1]),
                            gelu_exact(acc[i][2]), gelu_exact(acc[i][3]));
    }
    __syncthreads();

    #pragma unroll
    for (int i = 0; i < 64; i++) {
        int idx = tid + i*128;
        sW[(idx & 127)*68 + (idx >> 7)] = W3[idx];
    }
    __syncthreads();

    // ---- stage 3: OUT = W3 T + b3 (K=128)
    #pragma unroll
    for (int i = 0; i < 8; i++) {
        float bv = B3[r0 + i];
        #pragma unroll
        for (int j = 0; j < 4; j++) acc[i][j] = bv;
    }
    for (int k = 0; k < 128; k++) {
        float4 a0 = *(const float4*)&sW[k*68 + r0];
        float4 a1 = *(const float4*)&sW[k*68 + r0 + 4];
        float4 b  = *(const float4*)&sT[k*64 + x0];
        const float av[8] = {a0.x,a0.y,a0.z,a0.w,a1.x,a1.y,a1.z,a1.w};
        const float bv[4] = {b.x,b.y,b.z,b.w};
        #pragma unroll
        for (int i = 0; i < 8; i++)
            #pragma unroll
            for (int j = 0; j < 4; j++)
                acc[i][j] = fmaf(av[i], bv[j], acc[i][j]);
    }
    #pragma unroll
    for (int i = 0; i < 8; i++)
        *(float4*)&out[base + (r0+i)*NP + x0] =
            make_float4(acc[i][0],acc[i][1],acc[i][2],acc[i][3]);
}

// ---------------- S1: row DFT, Hermitian-halved, stores modes 0..32 only ---
__global__ void __launch_bounds__(264, 2) k_dft_rows() {
    extern __shared__ __align__(16) float2 fy_s[];   // 33 x 264
    const int bc = blockIdx.x;
    const int tid = threadIdx.x;
    for (int idx = tid; idx < 33*HP; idx += 264) {
        int m = idx / HP, y = idx % HP;
        float2 f;
        if (m < 32) f = g_Fy[m*HP + y];
        else { f = g_Fy[32*HP + y]; f.y = -f.y; }   // direct value for m=32
        fy_s[idx] = f;
    }
    __syncthreads();
    const int xt = tid % 66, rq = tid / 66;
    const int x0 = xt * 4, m0 = rq * 8;
    const float* img = g_x + bc*NP;
    float ar[9][4], ai[9][4];
    #pragma unroll
    for (int r = 0; r < 9; r++)
        #pragma unroll
        for (int j = 0; j < 4; j++) { ar[r][j] = 0.f; ai[r][j] = 0.f; }

    float4 vcur = __ldg((const float4*)(img + x0));
    for (int y = 0; y < HP; y++) {
        float4 vnext = vcur;
        if (y < HP-1) vnext = __ldg((const float4*)(img + (y+1)*HP + x0));
        const float vv[4] = {vcur.x, vcur.y, vcur.z, vcur.w};
        #pragma unroll
        for (int r = 0; r < 9; r++) {
            float2 f = fy_s[(m0 + r)*HP + y];
            #pragma unroll
            for (int j = 0; j < 4; j++) {
                ar[r][j] = fmaf(vv[j], f.x, ar[r][j]);
                ai[r][j] = fmaf(vv[j], f.y, ai[r][j]);
            }
        }
        vcur = vnext;
    }
    #pragma unroll
    for (int r = 0; r < 9; r++) {
        int m = m0 + r;   // 0..32; boundary duplicates write identical values
        float2* dst = &g_T1[(bc*33 + m)*HP + x0];
        #pragma unroll
        for (int j = 0; j < 4; j++) dst[j] = make_float2(ar[r][j], ai[r][j]);
    }
}

// ---------------- S2: col DFT via 4 cross-sums; each pass yields xf[m] & xf[64-m]
__global__ void __launch_bounds__(256) k_dft_cols() {
    extern __shared__ __align__(16) float2 t1s[];   // 33 x 264
    const int bc = blockIdx.x;
    const int tid = threadIdx.x;
    for (int idx = tid; idx < 33*HP; idx += 256)
        t1s[idx] = g_T1[bc*(33*HP) + idx];
    __syncthreads();
    const int k = tid & 31, rq = tid >> 5;   // rq 0..7; rows rq+8j (j=0..3); warp 0 also row 32
    float Sxx[4] = {0,0,0,0}, Syy[4] = {0,0,0,0}, Sxy[4] = {0,0,0,0}, Syx[4] = {0,0,0,0};
    float Txx = 0.f, Tyy = 0.f, Txy = 0.f, Tyx = 0.f;
    for (int x = 0; x < HP; x++) {
        float2 f = __ldg(&g_FxT[x*NM + k]);
        #pragma unroll
        for (int j = 0; j < 4; j++) {
            float2 p = t1s[(rq + 8*j)*HP + x];
            Sxx[j] = fmaf(p.x, f.x, Sxx[j]);
            Syy[j] = fmaf(p.y, f.y, Syy[j]);
            Sxy[j] = fmaf(p.x, f.y, Sxy[j]);
            Syx[j] = fmaf(p.y, f.x, Syx[j]);
        }
        if (rq == 0) {
            float2 p = t1s[32*HP + x];
            Txx = fmaf(p.x, f.x, Txx);
            Tyy = fmaf(p.y, f.y, Tyy);
            Txy = fmaf(p.x, f.y, Txy);
            Tyx = fmaf(p.y, f.x, Tyx);
        }
    }
    #pragma unroll
    for (int j = 0; j < 4; j++) {
        int m = rq + 8*j;   // 0..31
        g_xf[(bc*NR + m)*NM + k] = make_float2(Sxx[j] - Syy[j], Sxy[j] + Syx[j]);
        if (m >= 1)   // row 64-m holds conj(T1[m]) transform
            g_xf[(bc*NR + (64 - m))*NM + k] = make_float2(Sxx[j] + Syy[j], Sxy[j] - Syx[j]);
    }
    if (rq == 0)   // row 32 = ky 232 = conj of mode 32
        g_xf[(bc*NR + 32)*NM + k] = make_float2(Txx + Tyy, Txy - Tyx);
}

// ---------------- S3: channel mix, coalesced weight streaming --------------
// grid (4 o-quarters, 64 r); 256 thr = 32 k x 8 og; each thread: 2 o x 4 b.
__global__ void __launch_bounds__(256) k_chanmix(
    const float* __restrict__ w1r, const float* __restrict__ w1i,
    const float* __restrict__ w2r, const float* __restrict__ w2i)
{
    extern __shared__ __align__(16) float2 xs[];   // [b][i][k] = 4*64*32
    const int r = blockIdx.y, oh = blockIdx.x;
    const float* wr; const float* wi; int m1;
    if (r < 32) { wr = w1r; wi = w1i; m1 = r; }
    else        { wr = w2r; wi = w2i; m1 = r - 32; }
    const int tid = threadIdx.x;
    for (int idx = tid; idx < NB*NC*NM; idx += 256) {
        int b = idx >> 11, i = (idx >> 5) & 63, kk = idx & 31;
        xs[idx] = g_xf[((b*NC + i)*NR + r)*NM + kk];
    }
    __syncthreads();
    const int k = tid & 31, og = tid >> 5;
    const int o0 = oh*16 + og*2;
    const int woff = m1*NM + k;
    float ar[2][4], ai[2][4];
    #pragma unroll
    for (int oo = 0; oo < 2; oo++)
        #pragma unroll
        for (int b = 0; b < 4; b++) { ar[oo][b] = 0.f; ai[oo][b] = 0.f; }
    #pragma unroll 2
    for (int i = 0; i < NC; i++) {
        float wre0 = __ldg(&wr[(i*64 + o0    )*1024 + woff]);
        float wim0 = __ldg(&wi[(i*64 + o0    )*1024 + woff]);
        float wre1 = __ldg(&wr[(i*64 + o0 + 1)*1024 + woff]);
        float wim1 = __ldg(&wi[(i*64 + o0 + 1)*1024 + woff]);
        #pragma unroll
        for (int b = 0; b < 4; b++) {
            float2 xv = xs[(b*NC + i)*NM + k];
            ar[0][b] = fmaf(xv.x, wre0, fmaf(-xv.y, wim0, ar[0][b]));
            ai[0][b] = fmaf(xv.x, wim0, fmaf( xv.y, wre0, ai[0][b]));
            ar[1][b] = fmaf(xv.x, wre1, fmaf(-xv.y, wim1, ar[1][b]));
            ai[1][b] = fmaf(xv.x, wim1, fmaf( xv.y, wre1, ai[1][b]));
        }
    }
    #pragma unroll
    for (int oo = 0; oo < 2; oo++)
        #pragma unroll
        for (int b = 0; b < 4; b++)
            g_of[((b*NC + o0 + oo)*NR + r)*NM + k] = make_float2(ar[oo][b], ai[oo][b]);
}

// ---------------- fused inverse: S4 (iDFT ky) + S5 (real iDFT kx) ----------
template<bool LAST>
__global__ void __launch_bounds__(264) k_inv(float* __restrict__ out) {
    extern __shared__ __align__(16) float2 sm_inv[];
    float2* os = sm_inv;            // 64*32
    float2* Us = sm_inv + NR*NM;    // 264*32
    const int bo = blockIdx.x;
    const int tid = threadIdx.x;
    for (int idx = tid; idx < NR*NM; idx += 264)
        os[idx] = g_of[bo*(NR*NM) + idx];
    __syncthreads();

    // ---- phase A (S4)
    if (tid < 256) {
        const int k = tid & 31, yq = tid >> 5;
        for (int it = 0; it < 9; it++) {
            int yg = yq + it*8;
            if (yg >= 66) break;
            int y0 = yg * 4;
            float ar[4] = {0,0,0,0}, ai[4] = {0,0,0,0};
            for (int r = 0; r < NR; r++) {
                float2 o = os[r*NM + k];
                const float2* fp = &g_Fy[r*HP + y0];
                float4 fA = __ldg((const float4*)fp);
                float4 fB = __ldg((const float4*)(fp + 2));
                ar[0] = fmaf(o.x, fA.x, fmaf(o.y, fA.y, ar[0]));
                ai[0] = fmaf(o.y, fA.x, fmaf(-o.x, fA.y, ai[0]));
                ar[1] = fmaf(o.x, fA.z, fmaf(o.y, fA.w, ar[1]));
                ai[1] = fmaf(o.y, fA.z, fmaf(-o.x, fA.w, ai[1]));
                ar[2] = fmaf(o.x, fB.x, fmaf(o.y, fB.y, ar[2]));
                ai[2] = fmaf(o.y, fB.x, fmaf(-o.x, fB.y, ai[2]));
                ar[3] = fmaf(o.x, fB.z, fmaf(o.y, fB.w, ar[3]));
                ai[3] = fmaf(o.y, fB.z, fmaf(-o.x, fB.w, ai[3]));
            }
            #pragma unroll
            for (int j = 0; j < 4; j++)
                Us[(y0 + j)*NM + k] = make_float2(ar[j]*INV_HP, ai[j]*INV_HP);
        }
    }
    __syncthreads();

    // ---- phase B (S5)
    const int xt = tid % 33, yq = tid / 33;
    const int x0 = xt * 8;
    for (int p = 0; p < 9; p++) {
        int ybase = p*32 + yq*4;
        if (p == 8 && yq >= 2) break;
        float s[4][8];
        #pragma unroll
        for (int j = 0; j < 4; j++) {
            float u0 = Us[(ybase + j)*NM].x;
            #pragma unroll
            for (int q = 0; q < 8; q++) s[j][q] = u0;
        }
        for (int k = 1; k < NM; k++) {
            const float2* fp = &g_Fx[k*HP + x0];
            float4 fA = __ldg((const float4*)fp);
            float4 fB = __ldg((const float4*)(fp + 2));
            float4 fC = __ldg((const float4*)(fp + 4));
            float4 fD = __ldg((const float4*)(fp + 6));
            #pragma unroll
            for (int j = 0; j < 4; j++) {
                float2 u = Us[(ybase + j)*NM + k];
                float ux = 2.f*u.x, uy = 2.f*u.y;
                s[j][0]=fmaf(ux,fA.x,fmaf(uy,fA.y,s[j][0])); s[j][1]=fmaf(ux,fA.z,fmaf(uy,fA.w,s[j][1]));
                s[j][2]=fmaf(ux,fB.x,fmaf(uy,fB.y,s[j][2])); s[j][3]=fmaf(ux,fB.z,fmaf(uy,fB.w,s[j][3]));
                s[j][4]=fmaf(ux,fC.x,fmaf(uy,fC.y,s[j][4])); s[j][5]=fmaf(ux,fC.z,fmaf(uy,fC.w,s[j][5]));
                s[j][6]=fmaf(ux,fD.x,fmaf(uy,fD.y,s[j][6])); s[j][7]=fmaf(ux,fD.z,fmaf(uy,fD.w,s[j][7]));
            }
        }
        #pragma unroll
        for (int j = 0; j < 4; j++) {
            int y = ybase + j;
            int idx = bo*NP + y*HP + x0;
            float4 h0 = *(const float4*)&g_hbr[idx];
            float4 h1 = *(const float4*)&g_hbr[idx + 4];
            float4 r0 = make_float4(h0.x + s[j][0]*INV_HP, h0.y + s[j][1]*INV_HP,
                                    h0.z + s[j][2]*INV_HP, h0.w + s[j][3]*INV_HP);
            float4 r1 = make_float4(h1.x + s[j][4]*INV_HP, h1.y + s[j][5]*INV_HP,
                                    h1.z + s[j][6]*INV_HP, h1.w + s[j][7]*INV_HP);
            if (LAST) {
                if (y < H0 && x0 < W0) {
                    *(float4*)&out[bo*NPIX0 + y*W0 + x0]     = r0;
                    *(float4*)&out[bo*NPIX0 + y*W0 + x0 + 4] = r1;
                }
            } else {
                *(float4*)&g_x[idx]     = r0;
                *(float4*)&g_x[idx + 4] = r1;
            }
        }
    }
}

// ---------------- launch -----------------------------------------------------
extern "C" void kernel_launch(void* const* d_in, const int* in_sizes, int n_in,
                              void* d_out, int out_size)
{
    const float* x   = (const float*)d_in[0];
    const float* lw1 = (const float*)d_in[1];
    const float* lb1 = (const float*)d_in[2];
    const float* lw2 = (const float*)d_in[3];
    const float* lb2 = (const float*)d_in[4];
    const float* cw  = (const float*)d_in[5];
    const float* cb  = (const float*)d_in[6];
    const float* m1w = (const float*)d_in[7];
    const float* m1b = (const float*)d_in[8];
    const float* m2w = (const float*)d_in[9];
    const float* m2b = (const float*)d_in[10];
    const float* s1r = (const float*)d_in[11];
    const float* s1i = (const float*)d_in[12];
    const float* s2r = (const float*)d_in[13];
    const float* s2i = (const float*)d_in[14];
    float* out = (float*)d_out;

    float *px, *ph;
    cudaGetSymbolAddress((void**)&px, g_x);
    cudaGetSymbolAddress((void**)&ph, g_hbr);

    const int LOCAL_SMEM = 25088 * 4;            // 100352 B
    const int DFTR_SMEM  = 33 * HP * 8;          // 69696 B
    const int DFTC_SMEM  = 33 * HP * 8;          // 69696 B
    const int CMIX_SMEM  = NB*NC*NM * 8;         // 65536 B
    const int INV_SMEM   = (NR*NM + HP*NM) * 8;  // 83968 B
    cudaFuncSetAttribute(k_local,      cudaFuncAttributeMaxDynamicSharedMemorySize, LOCAL_SMEM);
    cudaFuncSetAttribute(k_dft_rows,   cudaFuncAttributeMaxDynamicSharedMemorySize, DFTR_SMEM);
    cudaFuncSetAttribute(k_dft_cols,   cudaFuncAttributeMaxDynamicSharedMemorySize, DFTC_SMEM);
    cudaFuncSetAttribute(k_chanmix,    cudaFuncAttributeMaxDynamicSharedMemorySize, CMIX_SMEM);
    cudaFuncSetAttribute(k_inv<false>, cudaFuncAttributeMaxDynamicSharedMemorySize, INV_SMEM);
    cudaFuncSetAttribute(k_inv<true >, cudaFuncAttributeMaxDynamicSharedMemorySize, INV_SMEM);

    k_tables<<<132, 256>>>();
    k_zero_x<<<4096, 256>>>();
    k_lift<<<dim3(256, NB), 256>>>(x, lw1, lb1, lw2, lb2);

    for (int L = 0; L < 3; L++) {
        k_local<<<dim3(NP/64, NB), 128, LOCAL_SMEM>>>(
            px, ph,
            cw  + L*64*64,   cb  + L*64,
            m1w + L*128*64,  m1b + L*128,
            m2w + L*64*128,  m2b + L*64);
        k_dft_rows<<<NB*NC, 264, DFTR_SMEM>>>();
        k_dft_cols<<<NB*NC, 256, DFTC_SMEM>>>();
        k_chanmix<<<dim3(4, 64), 256, CMIX_SMEM>>>(s1r + L*SPW, s1i + L*SPW, s2r + L*SPW, s2i + L*SPW);
        if (L < 2) k_inv<false><<<NB*NC, 264, INV_SMEM>>>(out);
        else       k_inv<true ><<<NB*NC, 264, INV_SMEM>>>(out);
    }
}

// round 7
// speedup vs baseline: 2.1961x; 1.3399x over previous
#include <cuda_runtime.h>
#include <math.h>

#define NB 4
#define CIN 3
#define NC 64
#define H0 256
#define W0 256
#define NPIX0 (H0*W0)
#define HP 264
#define NP (HP*HP)      /* 69696 */
#define NR 64
#define NM 32
#define SPW (64*64*32*32)
#define INV_HP (1.0f/264.0f)

// ---------------- scratch ----------------------------------------------------
__device__ float  g_x  [NB*NC*NP];
__device__ float  g_hbr[NB*NC*NP];
__device__ float2 g_T1 [NB*NC*33*HP];  // row-DFT, modes 0..32 (Hermitian)
__device__ float2 g_xf [NB*NC*NR*NM];
__device__ float2 g_of [NB*NC*NR*NM];
__device__ float2 g_Fy [NR*HP];
__device__ float2 g_Fx [NM*HP];
__device__ float2 g_FxT[HP*NM];
__device__ float  g_WfT[3*64*128];   // fused (mlp_w1@conv_w)^T : [L][k][o]
__device__ float  g_W3T[3*128*64];   // mlp_w2^T : [L][k][o]
__device__ float  g_bf [3*128];      // fused bias

__device__ __forceinline__ float gelu_exact(float v) {
    return 0.5f * v * (1.0f + erff(v * 0.70710678118654752440f));
}

// ---------------- init --------------------------------------------------------
__global__ void k_tables() {
    int idx = blockIdx.x * 256 + threadIdx.x;
    if (idx < NR*HP) {
        int r = idx / HP, y = idx % HP;
        int ky = (r < 32) ? r : r + 200;
        int m = (ky * y) % HP;
        double a = 6.283185307179586 * (double)m / (double)HP;
        g_Fy[idx] = make_float2((float)cos(a), (float)(-sin(a)));
    } else if (idx < NR*HP + NM*HP) {
        int j = idx - NR*HP;
        int k = j / HP, xx = j % HP;
        int m = (k * xx) % HP;
        double a = 6.283185307179586 * (double)m / (double)HP;
        float2 f = make_float2((float)cos(a), (float)(-sin(a)));
        g_Fx[j] = f;
        g_FxT[xx*NM + k] = f;
    }
}

// fuse conv into mlp1; transpose weights to [k][o]
__global__ void k_wfuse(const float* __restrict__ cw,  const float* __restrict__ cb,
                        const float* __restrict__ m1w, const float* __restrict__ m1b,
                        const float* __restrict__ m2w) {
    int idx = blockIdx.x * 256 + threadIdx.x;
    if (idx < 3*8192) {                 // WfT[L][k][o] = sum_j m1w[L][o][j]*cw[L][j][k]
        int L = idx / 8192, r = idx % 8192, k = r >> 7, o = r & 127;
        const float* W2 = m1w + L*8192;
        const float* W1 = cw  + L*4096;
        float s = 0.f;
        for (int j = 0; j < 64; j++) s = fmaf(W2[o*64 + j], W1[j*64 + k], s);
        g_WfT[idx] = s;
    } else if (idx < 6*8192) {          // W3T[L][k][o] = m2w[L][o][k]
        int i = idx - 3*8192;
        int L = i / 8192, r = i % 8192, k = r >> 6, o = r & 63;
        g_W3T[i] = m2w[L*8192 + o*128 + k];
    } else if (idx < 6*8192 + 384) {    // bf[L][o] = m1w[L][o]@cb[L] + m1b[L][o]
        int i = idx - 6*8192;
        int L = i / 128, o = i % 128;
        const float* W2 = m1w + L*8192;
        float s = m1b[L*128 + o];
        for (int j = 0; j < 64; j++) s = fmaf(W2[o*64 + j], cb[L*64 + j], s);
        g_bf[i] = s;
    }
}

__global__ void k_zero_x() {
    int n = NB*NC*NP;
    for (int i = blockIdx.x * 256 + threadIdx.x; i < n; i += gridDim.x * 256)
        g_x[i] = 0.0f;
}

// ---------------- lift: 5 -> 32 (GELU) -> 64 -------------------------------
__global__ void __launch_bounds__(256) k_lift(
    const float* __restrict__ x,
    const float* __restrict__ w1, const float* __restrict__ b1,
    const float* __restrict__ w2, const float* __restrict__ b2)
{
    __shared__ float sw1[32*5], sb1[32], sw2[64*32], sb2[64];
    for (int i = threadIdx.x; i < 160;  i += 256) sw1[i] = w1[i];
    for (int i = threadIdx.x; i < 32;   i += 256) sb1[i] = b1[i];
    for (int i = threadIdx.x; i < 2048; i += 256) sw2[i] = w2[i];
    for (int i = threadIdx.x; i < 64;   i += 256) sb2[i] = b2[i];
    __syncthreads();
    int b = blockIdx.y;
    int p = blockIdx.x * 256 + threadIdx.x;
    int i = p >> 8, j = p & 255;
    float f[5];
    f[0] = x[(b*CIN + 0)*NPIX0 + p];
    f[1] = x[(b*CIN + 1)*NPIX0 + p];
    f[2] = x[(b*CIN + 2)*NPIX0 + p];
    f[3] = (float)i * (1.0f/255.0f);
    f[4] = (float)j * (1.0f/255.0f);
    float h[32];
    #pragma unroll
    for (int c1 = 0; c1 < 32; c1++) {
        float v = sb1[c1];
        #pragma unroll
        for (int q = 0; q < 5; q++) v = fmaf(sw1[c1*5+q], f[q], v);
        h[c1] = gelu_exact(v);
    }
    int base = b*NC*NP + i*HP + j;
    for (int c2 = 0; c2 < 64; c2++) {
        float v = sb2[c2];
        #pragma unroll
        for (int c1 = 0; c1 < 32; c1++) v = fmaf(sw2[c2*32+c1], h[c1], v);
        g_x[base + c2*NP] = v;
    }
}

// ---------------- fused local branch: gelu(Wf x + bf) -> W3 -----------------
__global__ void __launch_bounds__(128, 2) k_local(
    const float* __restrict__ in, float* __restrict__ out,
    const float* __restrict__ WfT, const float* __restrict__ Bf,
    const float* __restrict__ W3T, const float* __restrict__ B3)
{
    extern __shared__ __align__(16) float sm_local[];
    float* sX = sm_local;           // 64x64
    float* sT = sm_local + 4096;    // 128x64
    float* sW = sm_local + 12288;   // 8192 floats
    const int tid = threadIdx.x;
    const int ty = tid >> 4, tx = tid & 15;   // 8 x 16
    const int r0 = ty * 8, x0 = tx * 4;
    const int base = blockIdx.y * (NC*NP) + blockIdx.x * 64;

    #pragma unroll
    for (int i = 0; i < 32; i++) {
        int idx = tid + i*128;
        sX[idx] = in[base + (idx >> 6)*NP + (idx & 63)];
    }
    #pragma unroll
    for (int i = 0; i < 64; i++) {
        int idx = tid + i*128;
        sW[idx] = WfT[idx];
    }
    __syncthreads();

    float acc[8][4];
    // ---- stage A: T = gelu(Wf X + bf), 128 rows in 2 halves (K=64)
    #pragma unroll
    for (int h = 0; h < 2; h++) {
        #pragma unroll
        for (int i = 0; i < 8; i++) {
            float bv = __ldg(&Bf[h*64 + r0 + i]);
            #pragma unroll
            for (int j = 0; j < 4; j++) acc[i][j] = bv;
        }
        for (int k = 0; k < 64; k++) {
            float4 a0 = *(const float4*)&sW[k*128 + h*64 + r0];
            float4 a1 = *(const float4*)&sW[k*128 + h*64 + r0 + 4];
            float4 b  = *(const float4*)&sX[k*64 + x0];
            const float av[8] = {a0.x,a0.y,a0.z,a0.w,a1.x,a1.y,a1.z,a1.w};
            const float bv[4] = {b.x,b.y,b.z,b.w};
            #pragma unroll
            for (int i = 0; i < 8; i++)
                #pragma unroll
                for (int j = 0; j < 4; j++)
                    acc[i][j] = fmaf(av[i], bv[j], acc[i][j]);
        }
        #pragma unroll
        for (int i = 0; i < 8; i++)
            *(float4*)&sT[(h*64 + r0 + i)*64 + x0] =
                make_float4(gelu_exact(acc[i][0]), gelu_exact(acc[i][1]),
                            gelu_exact(acc[i][2]), gelu_exact(acc[i][3]));
    }
    __syncthreads();

    #pragma unroll
    for (int i = 0; i < 64; i++) {
        int idx = tid + i*128;
        sW[idx] = W3T[idx];
    }
    __syncthreads();

    // ---- stage B: OUT = W3 T + b3 (K=128)
    #pragma unroll
    for (int i = 0; i < 8; i++) {
        float bv = __ldg(&B3[r0 + i]);
        #pragma unroll
        for (int j = 0; j < 4; j++) acc[i][j] = bv;
    }
    for (int k = 0; k < 128; k++) {
        float4 a0 = *(const float4*)&sW[k*64 + r0];
        float4 a1 = *(const float4*)&sW[k*64 + r0 + 4];
        float4 b  = *(const float4*)&sT[k*64 + x0];
        const float av[8] = {a0.x,a0.y,a0.z,a0.w,a1.x,a1.y,a1.z,a1.w};
        const float bv[4] = {b.x,b.y,b.z,b.w};
        #pragma unroll
        for (int i = 0; i < 8; i++)
            #pragma unroll
            for (int j = 0; j < 4; j++)
                acc[i][j] = fmaf(av[i], bv[j], acc[i][j]);
    }
    #pragma unroll
    for (int i = 0; i < 8; i++)
        *(float4*)&out[base + (r0+i)*NP + x0] =
            make_float4(acc[i][0],acc[i][1],acc[i][2],acc[i][3]);
}

// ---------------- S1: row DFT with y-pair symmetry --------------------------
__global__ void __launch_bounds__(264, 2) k_dft_rows() {
    extern __shared__ __align__(16) float2 fy_s[];   // 33 x 264
    const int bc = blockIdx.x;
    const int tid = threadIdx.x;
    for (int idx = tid; idx < 33*HP; idx += 264) {
        int m = idx / HP, y = idx % HP;
        float2 f;
        if (m < 32) f = g_Fy[m*HP + y];
        else { f = g_Fy[32*HP + y]; f.y = -f.y; }
        fy_s[idx] = f;
    }
    __syncthreads();
    const int xt = tid % 66, rq = tid / 66;
    const int x0 = xt * 4, m0 = rq * 8;
    const float* img = g_x + bc*NP;
    float ar[9][4], ai[9][4];
    #pragma unroll
    for (int r = 0; r < 9; r++)
        #pragma unroll
        for (int j = 0; j < 4; j++) { ar[r][j] = 0.f; ai[r][j] = 0.f; }

    // y pairs (y, 264-y), y = 1..131
    float4 va = __ldg((const float4*)(img + HP + x0));
    float4 vb = __ldg((const float4*)(img + 263*HP + x0));
    for (int y = 1; y <= 131; y++) {
        float4 na = va, nb = vb;
        if (y < 131) {
            na = __ldg((const float4*)(img + (y+1)*HP + x0));
            nb = __ldg((const float4*)(img + (263-y)*HP + x0));
        }
        const float pp[4] = {va.x+vb.x, va.y+vb.y, va.z+vb.z, va.w+vb.w};
        const float dd[4] = {va.x-vb.x, va.y-vb.y, va.z-vb.z, va.w-vb.w};
        #pragma unroll
        for (int r = 0; r < 9; r++) {
            float2 f = fy_s[(m0 + r)*HP + y];
            #pragma unroll
            for (int j = 0; j < 4; j++) {
                ar[r][j] = fmaf(pp[j], f.x, ar[r][j]);
                ai[r][j] = fmaf(dd[j], f.y, ai[r][j]);
            }
        }
        va = na; vb = nb;
    }
    // singles y=0 (cos=1,sin=0) and y=132 (sin=0)
    {
        float4 v0   = __ldg((const float4*)(img + x0));
        float4 v132 = __ldg((const float4*)(img + 132*HP + x0));
        const float z0[4]  = {v0.x, v0.y, v0.z, v0.w};
        const float z1[4]  = {v132.x, v132.y, v132.z, v132.w};
        #pragma unroll
        for (int r = 0; r < 9; r++) {
            float c132 = fy_s[(m0 + r)*HP + 132].x;
            #pragma unroll
            for (int j = 0; j < 4; j++)
                ar[r][j] = fmaf(z1[j], c132, ar[r][j] + z0[j]);
        }
    }
    #pragma unroll
    for (int r = 0; r < 9; r++) {
        int m = m0 + r;   // 0..32 (boundary duplicates write identical values)
        float2* dst = &g_T1[(bc*33 + m)*HP + x0];
        #pragma unroll
        for (int j = 0; j < 4; j++) dst[j] = make_float2(ar[r][j], ai[r][j]);
    }
}

// ---------------- S2: col DFT via 4 cross-sums (unchanged) ------------------
__global__ void __launch_bounds__(256) k_dft_cols() {
    extern __shared__ __align__(16) float2 t1s[];   // 33 x 264
    const int bc = blockIdx.x;
    const int tid = threadIdx.x;
    for (int idx = tid; idx < 33*HP; idx += 256)
        t1s[idx] = g_T1[bc*(33*HP) + idx];
    __syncthreads();
    const int k = tid & 31, rq = tid >> 5;
    float Sxx[4] = {0,0,0,0}, Syy[4] = {0,0,0,0}, Sxy[4] = {0,0,0,0}, Syx[4] = {0,0,0,0};
    float Txx = 0.f, Tyy = 0.f, Txy = 0.f, Tyx = 0.f;
    for (int x = 0; x < HP; x++) {
        float2 f = __ldg(&g_FxT[x*NM + k]);
        #pragma unroll
        for (int j = 0; j < 4; j++) {
            float2 p = t1s[(rq + 8*j)*HP + x];
            Sxx[j] = fmaf(p.x, f.x, Sxx[j]);
            Syy[j] = fmaf(p.y, f.y, Syy[j]);
            Sxy[j] = fmaf(p.x, f.y, Sxy[j]);
            Syx[j] = fmaf(p.y, f.x, Syx[j]);
        }
        if (rq == 0) {
            float2 p = t1s[32*HP + x];
            Txx = fmaf(p.x, f.x, Txx);
            Tyy = fmaf(p.y, f.y, Tyy);
            Txy = fmaf(p.x, f.y, Txy);
            Tyx = fmaf(p.y, f.x, Tyx);
        }
    }
    #pragma unroll
    for (int j = 0; j < 4; j++) {
        int m = rq + 8*j;
        g_xf[(bc*NR + m)*NM + k] = make_float2(Sxx[j] - Syy[j], Sxy[j] + Syx[j]);
        if (m >= 1)
            g_xf[(bc*NR + (64 - m))*NM + k] = make_float2(Sxx[j] + Syy[j], Sxy[j] - Syx[j]);
    }
    if (rq == 0)
        g_xf[(bc*NR + 32)*NM + k] = make_float2(Txx + Tyy, Txy - Tyx);
}

// ---------------- S3: channel mix (unchanged) --------------------------------
__global__ void __launch_bounds__(256) k_chanmix(
    const float* __restrict__ w1r, const float* __restrict__ w1i,
    const float* __restrict__ w2r, const float* __restrict__ w2i)
{
    extern __shared__ __align__(16) float2 xs[];   // 4*64*32
    const int r = blockIdx.y, oh = blockIdx.x;
    const float* wr; const float* wi; int m1;
    if (r < 32) { wr = w1r; wi = w1i; m1 = r; }
    else        { wr = w2r; wi = w2i; m1 = r - 32; }
    const int tid = threadIdx.x;
    for (int idx = tid; idx < NB*NC*NM; idx += 256) {
        int b = idx >> 11, i = (idx >> 5) & 63, kk = idx & 31;
        xs[idx] = g_xf[((b*NC + i)*NR + r)*NM + kk];
    }
    __syncthreads();
    const int k = tid & 31, og = tid >> 5;
    const int o0 = oh*16 + og*2;
    const int woff = m1*NM + k;
    float ar[2][4], ai[2][4];
    #pragma unroll
    for (int oo = 0; oo < 2; oo++)
        #pragma unroll
        for (int b = 0; b < 4; b++) { ar[oo][b] = 0.f; ai[oo][b] = 0.f; }
    #pragma unroll 2
    for (int i = 0; i < NC; i++) {
        float wre0 = __ldg(&wr[(i*64 + o0    )*1024 + woff]);
        float wim0 = __ldg(&wi[(i*64 + o0    )*1024 + woff]);
        float wre1 = __ldg(&wr[(i*64 + o0 + 1)*1024 + woff]);
        float wim1 = __ldg(&wi[(i*64 + o0 + 1)*1024 + woff]);
        #pragma unroll
        for (int b = 0; b < 4; b++) {
            float2 xv = xs[(b*NC + i)*NM + k];
            ar[0][b] = fmaf(xv.x, wre0, fmaf(-xv.y, wim0, ar[0][b]));
            ai[0][b] = fmaf(xv.x, wim0, fmaf( xv.y, wre0, ai[0][b]));
            ar[1][b] = fmaf(xv.x, wre1, fmaf(-xv.y, wim1, ar[1][b]));
            ai[1][b] = fmaf(xv.x, wim1, fmaf( xv.y, wre1, ai[1][b]));
        }
    }
    #pragma unroll
    for (int oo = 0; oo < 2; oo++)
        #pragma unroll
        for (int b = 0; b < 4; b++)
            g_of[((b*NC + o0 + oo)*NR + r)*NM + k] = make_float2(ar[oo][b], ai[oo][b]);
}

// ---------------- fused inverse, pair symmetry in both phases ----------------
template<bool LAST>
__global__ void __launch_bounds__(272) k_inv(float* __restrict__ out) {
    extern __shared__ __align__(16) float2 sm_inv[];
    float2* os = sm_inv;            // 64*32 -> transformed to P/Q in place
    float2* Us = sm_inv + 2048;     // 264*32
    const int bo = blockIdx.x;
    const int tid = threadIdx.x;
    for (int idx = tid; idx < 2048; idx += 272)
        os[idx] = g_of[bo*2048 + idx];
    __syncthreads();
    // in-place pair transform: row m := (P.x, Q.y), row 64-m := (P.y, Q.x)
    for (int idx = tid; idx < 31*32; idx += 272) {
        int m = (idx >> 5) + 1, k = idx & 31;
        float2 A = os[m*NM + k], B = os[(64 - m)*NM + k];
        os[m*NM + k]        = make_float2(A.x + B.x, A.y - B.y);
        os[(64 - m)*NM + k] = make_float2(A.y + B.y, A.x - B.x);
    }
    __syncthreads();

    // ---- phase A: U[y,k]; 31 pairs at 4 FMA each + rows 0,32
    if (tid < 256) {
        const int k = tid & 31, yq = tid >> 5;
        const float2 o0  = os[k];
        const float2 o32 = os[32*NM + k];
        for (int it = 0; it < 9; it++) {
            int yg = yq + it*8;
            if (yg >= 66) break;
            int y0 = yg * 4;
            float re[4], im[4];
            {
                const float2* fp = &g_Fy[32*HP + y0];
                float4 fA = __ldg((const float4*)fp);
                float4 fB = __ldg((const float4*)(fp + 2));
                re[0] = o0.x + o32.x*fA.x - o32.y*fA.y;  im[0] = o0.y + o32.y*fA.x + o32.x*fA.y;
                re[1] = o0.x + o32.x*fA.z - o32.y*fA.w;  im[1] = o0.y + o32.y*fA.z + o32.x*fA.w;
                re[2] = o0.x + o32.x*fB.x - o32.y*fB.y;  im[2] = o0.y + o32.y*fB.x + o32.x*fB.y;
                re[3] = o0.x + o32.x*fB.z - o32.y*fB.w;  im[3] = o0.y + o32.y*fB.z + o32.x*fB.w;
            }
            #pragma unroll 4
            for (int m = 1; m <= 31; m++) {
                float2 Ps = os[m*NM + k];
                float2 Qs = os[(64 - m)*NM + k];
                const float2* fp = &g_Fy[m*HP + y0];
                float4 fA = __ldg((const float4*)fp);
                float4 fB = __ldg((const float4*)(fp + 2));
                re[0] = fmaf(Ps.x, fA.x, fmaf( Ps.y, fA.y, re[0]));
                im[0] = fmaf(Qs.x, fA.x, fmaf(-Qs.y, fA.y, im[0]));
                re[1] = fmaf(Ps.x, fA.z, fmaf( Ps.y, fA.w, re[1]));
                im[1] = fmaf(Qs.x, fA.z, fmaf(-Qs.y, fA.w, im[1]));
                re[2] = fmaf(Ps.x, fB.x, fmaf( Ps.y, fB.y, re[2]));
                im[2] = fmaf(Qs.x, fB.x, fmaf(-Qs.y, fB.y, im[2]));
                re[3] = fmaf(Ps.x, fB.z, fmaf( Ps.y, fB.w, re[3]));
                im[3] = fmaf(Qs.x, fB.z, fmaf(-Qs.y, fB.w, im[3]));
            }
            #pragma unroll
            for (int j = 0; j < 4; j++)
                Us[(y0 + j)*NM + k] = make_float2(re[j]*INV_HP, im[j]*INV_HP);
        }
    }
    __syncthreads();

    // ---- phase B: x-pair symmetry. xt 0..33 -> x0 = xt*4 (0..132+)
    const int xt = tid % 34, yq2 = tid / 34;   // yq2 0..7
    const int x0 = xt * 4;
    for (int p = 0; p < 9; p++) {
        int ybase = p*32 + yq2*4;
        if (p == 8 && yq2 >= 2) break;
        float E[4][4], O[4][4], u0[4];
        #pragma unroll
        for (int j = 0; j < 4; j++) {
            u0[j] = Us[(ybase + j)*NM].x;
            #pragma unroll
            for (int q = 0; q < 4; q++) { E[j][q] = 0.f; O[j][q] = 0.f; }
        }
        for (int k = 1; k < NM; k++) {
            const float2* fp = &g_Fx[k*HP + x0];
            float4 fA = __ldg((const float4*)fp);
            float4 fB = __ldg((const float4*)(fp + 2));
            #pragma unroll
            for (int j = 0; j < 4; j++) {
                float2 u = Us[(ybase + j)*NM + k];
                E[j][0] = fmaf(u.x, fA.x, E[j][0]);  O[j][0] = fmaf(u.y, fA.y, O[j][0]);
                E[j][1] = fmaf(u.x, fA.z, E[j][1]);  O[j][1] = fmaf(u.y, fA.w, O[j][1]);
                E[j][2] = fmaf(u.x, fB.x, E[j][2]);  O[j][2] = fmaf(u.y, fB.y, O[j][2]);
                E[j][3] = fmaf(u.x, fB.z, E[j][3]);  O[j][3] = fmaf(u.y, fB.w, O[j][3]);
            }
        }
        #pragma unroll
        for (int j = 0; j < 4; j++) {
            int y = ybase + j;
            if (xt < 33) {
                int idx = bo*NP + y*HP + x0;
                float4 h = *(const float4*)&g_hbr[idx];
                float4 rv = make_float4(
                    h.x + (u0[j] + 2.f*(E[j][0] + O[j][0]))*INV_HP,
                    h.y + (u0[j] + 2.f*(E[j][1] + O[j][1]))*INV_HP,
                    h.z + (u0[j] + 2.f*(E[j][2] + O[j][2]))*INV_HP,
                    h.w + (u0[j] + 2.f*(E[j][3] + O[j][3]))*INV_HP);
                if (LAST) { if (y < H0) *(float4*)&out[bo*NPIX0 + y*W0 + x0] = rv; }
                else      *(float4*)&g_x[idx] = rv;
                #pragma unroll
                for (int q = 0; q < 4; q++) {
                    if (xt == 0 && q == 0) continue;   // x=0 has no mirror
                    int xm = 264 - (x0 + q);
                    float hm = __ldg(&g_hbr[bo*NP + y*HP + xm]);
                    float vm = hm + (u0[j] + 2.f*(E[j][q] - O[j][q]))*INV_HP;
                    if (LAST) { if (y < H0 && xm < W0) out[bo*NPIX0 + y*W0 + xm] = vm; }
                    else      g_x[bo*NP + y*HP + xm] = vm;
                }
            } else {   // xt == 33: x = 132 only (self-mirror)
                int idx = bo*NP + y*HP + 132;
                float hm = __ldg(&g_hbr[idx]);
                float vm = hm + (u0[j] + 2.f*(E[j][0] + O[j][0]))*INV_HP;
                if (LAST) { if (y < H0) out[bo*NPIX0 + y*W0 + 132] = vm; }
                else      g_x[idx] = vm;
            }
        }
    }
}

// ---------------- launch -----------------------------------------------------
extern "C" void kernel_launch(void* const* d_in, const int* in_sizes, int n_in,
                              void* d_out, int out_size)
{
    const float* x   = (const float*)d_in[0];
    const float* lw1 = (const float*)d_in[1];
    const float* lb1 = (const float*)d_in[2];
    const float* lw2 = (const float*)d_in[3];
    const float* lb2 = (const float*)d_in[4];
    const float* cw  = (const float*)d_in[5];
    const float* cb  = (const float*)d_in[6];
    const float* m1w = (const float*)d_in[7];
    const float* m1b = (const float*)d_in[8];
    const float* m2w = (const float*)d_in[9];
    const float* m2b = (const float*)d_in[10];
    const float* s1r = (const float*)d_in[11];
    const float* s1i = (const float*)d_in[12];
    const float* s2r = (const float*)d_in[13];
    const float* s2i = (const float*)d_in[14];
    float* out = (float*)d_out;

    float *px, *ph, *pwf, *pw3, *pbf;
    cudaGetSymbolAddress((void**)&px,  g_x);
    cudaGetSymbolAddress((void**)&ph,  g_hbr);
    cudaGetSymbolAddress((void**)&pwf, g_WfT);
    cudaGetSymbolAddress((void**)&pw3, g_W3T);
    cudaGetSymbolAddress((void**)&pbf, g_bf);

    const int LOCAL_SMEM = 20480 * 4;            // 81920 B
    const int DFTR_SMEM  = 33 * HP * 8;          // 69696 B
    const int DFTC_SMEM  = 33 * HP * 8;          // 69696 B
    const int CMIX_SMEM  = NB*NC*NM * 8;         // 65536 B
    const int INV_SMEM   = (NR*NM + HP*NM) * 8;  // 83968 B
    cudaFuncSetAttribute(k_local,      cudaFuncAttributeMaxDynamicSharedMemorySize, LOCAL_SMEM);
    cudaFuncSetAttribute(k_dft_rows,   cudaFuncAttributeMaxDynamicSharedMemorySize, DFTR_SMEM);
    cudaFuncSetAttribute(k_dft_cols,   cudaFuncAttributeMaxDynamicSharedMemorySize, DFTC_SMEM);
    cudaFuncSetAttribute(k_chanmix,    cudaFuncAttributeMaxDynamicSharedMemorySize, CMIX_SMEM);
    cudaFuncSetAttribute(k_inv<false>, cudaFuncAttributeMaxDynamicSharedMemorySize, INV_SMEM);
    cudaFuncSetAttribute(k_inv<true >, cudaFuncAttributeMaxDynamicSharedMemorySize, INV_SMEM);

    k_tables<<<132, 256>>>();
    k_wfuse<<<194, 256>>>(cw, cb, m1w, m1b, m2w);
    k_zero_x<<<4096, 256>>>();
    k_lift<<<dim3(256, NB), 256>>>(x, lw1, lb1, lw2, lb2);

    for (int L = 0; L < 3; L++) {
        k_local<<<dim3(NP/64, NB), 128, LOCAL_SMEM>>>(
            px, ph, pwf + L*8192, pbf + L*128, pw3 + L*8192, m2b + L*64);
        k_dft_rows<<<NB*NC, 264, DFTR_SMEM>>>();
        k_dft_cols<<<NB*NC, 256, DFTC_SMEM>>>();
        k_chanmix<<<dim3(4, 64), 256, CMIX_SMEM>>>(s1r + L*SPW, s1i + L*SPW, s2r + L*SPW, s2i + L*SPW);
        if (L < 2) k_inv<false><<<NB*NC, 272, INV_SMEM>>>(out);
        else       k_inv<true ><<<NB*NC, 272, INV_SMEM>>>(out);
    }
}

// round 8
// speedup vs baseline: 2.4331x; 1.1079x over previous
#include <cuda_runtime.h>
#include <math.h>

#define NB 4
#define CIN 3
#define NC 64
#define H0 256
#define W0 256
#define NPIX0 (H0*W0)
#define HP 264
#define NP (HP*HP)      /* 69696 */
#define NR 64
#define NM 32
#define SPW (64*64*32*32)
#define INV_HP (1.0f/264.0f)

typedef unsigned long long u64;

// ---------------- f32x2 packed-FMA helpers (Blackwell dual-lane fp32) -------
__device__ __forceinline__ u64 pk(float lo, float hi) {
    u64 r; asm("mov.b64 %0, {%1, %2};" : "=l"(r) : "f"(lo), "f"(hi)); return r;
}
__device__ __forceinline__ u64 pkdup(float v) { return pk(v, v); }
__device__ __forceinline__ float2 up(u64 v) {
    float lo, hi; asm("mov.b64 {%0, %1}, %2;" : "=f"(lo), "=f"(hi) : "l"(v));
    return make_float2(lo, hi);
}
__device__ __forceinline__ u64 f2fma(u64 a, u64 b, u64 c) {
    u64 d; asm("fma.rn.f32x2 %0, %1, %2, %3;" : "=l"(d) : "l"(a), "l"(b), "l"(c)); return d;
}
__device__ __forceinline__ u64 f2add(u64 a, u64 b) {
    u64 d; asm("add.rn.f32x2 %0, %1, %2;" : "=l"(d) : "l"(a), "l"(b)); return d;
}

// ---------------- scratch ----------------------------------------------------
__device__ float  g_x  [NB*NC*NP];
__device__ float  g_hbr[NB*NC*NP];
__device__ float2 g_T1 [NB*NC*33*HP];
__device__ float2 g_xf [NB*NC*NR*NM];
__device__ float2 g_of [NB*NC*NR*NM];
__device__ float2 g_Fy [NR*HP];
__device__ float2 g_Fx [NM*HP];
__device__ float2 g_FxT[HP*NM];
__device__ float  g_Fyc[33*HP];      // split cos (= g_Fy[m].x) for modes 0..32
__device__ float  g_Fys[33*HP];      // split "sin" (= g_Fy[m].y)
__device__ float  g_WfT[3*64*128];
__device__ float  g_W3T[3*128*64];
__device__ float  g_bf [3*128];

__device__ __forceinline__ float gelu_exact(float v) {
    return 0.5f * v * (1.0f + erff(v * 0.70710678118654752440f));
}

// ---------------- init --------------------------------------------------------
__global__ void k_tables() {
    int idx = blockIdx.x * 256 + threadIdx.x;
    if (idx < NR*HP) {
        int r = idx / HP, y = idx % HP;
        int ky = (r < 32) ? r : r + 200;
        int m = (ky * y) % HP;
        double a = 6.283185307179586 * (double)m / (double)HP;
        float2 f = make_float2((float)cos(a), (float)(-sin(a)));
        g_Fy[idx] = f;
        if (r <= 32) { g_Fyc[r*HP + y] = f.x; g_Fys[r*HP + y] = f.y; }
    } else if (idx < NR*HP + NM*HP) {
        int j = idx - NR*HP;
        int k = j / HP, xx = j % HP;
        int m = (k * xx) % HP;
        double a = 6.283185307179586 * (double)m / (double)HP;
        float2 f = make_float2((float)cos(a), (float)(-sin(a)));
        g_Fx[j] = f;
        g_FxT[xx*NM + k] = f;
    }
}

// fuse conv into mlp1 (double accumulation); transpose weights to [k][o]
__global__ void k_wfuse(const float* __restrict__ cw,  const float* __restrict__ cb,
                        const float* __restrict__ m1w, const float* __restrict__ m1b,
                        const float* __restrict__ m2w) {
    int idx = blockIdx.x * 256 + threadIdx.x;
    if (idx < 3*8192) {
        int L = idx / 8192, r = idx % 8192, k = r >> 7, o = r & 127;
        const float* W2 = m1w + L*8192;
        const float* W1 = cw  + L*4096;
        double s = 0.0;
        for (int j = 0; j < 64; j++) s += (double)W2[o*64 + j] * (double)W1[j*64 + k];
        g_WfT[idx] = (float)s;
    } else if (idx < 6*8192) {
        int i = idx - 3*8192;
        int L = i / 8192, r = i % 8192, k = r >> 6, o = r & 63;
        g_W3T[i] = m2w[L*8192 + o*128 + k];
    } else if (idx < 6*8192 + 384) {
        int i = idx - 6*8192;
        int L = i / 128, o = i % 128;
        const float* W2 = m1w + L*8192;
        double s = (double)m1b[L*128 + o];
        for (int j = 0; j < 64; j++) s += (double)W2[o*64 + j] * (double)cb[L*64 + j];
        g_bf[i] = (float)s;
    }
}

__global__ void k_zero_x() {
    int n = NB*NC*NP;
    for (int i = blockIdx.x * 256 + threadIdx.x; i < n; i += gridDim.x * 256)
        g_x[i] = 0.0f;
}

// ---------------- lift: 5 -> 32 (GELU) -> 64 -------------------------------
__global__ void __launch_bounds__(256) k_lift(
    const float* __restrict__ x,
    const float* __restrict__ w1, const float* __restrict__ b1,
    const float* __restrict__ w2, const float* __restrict__ b2)
{
    __shared__ float sw1[32*5], sb1[32], sw2[64*32], sb2[64];
    for (int i = threadIdx.x; i < 160;  i += 256) sw1[i] = w1[i];
    for (int i = threadIdx.x; i < 32;   i += 256) sb1[i] = b1[i];
    for (int i = threadIdx.x; i < 2048; i += 256) sw2[i] = w2[i];
    for (int i = threadIdx.x; i < 64;   i += 256) sb2[i] = b2[i];
    __syncthreads();
    int b = blockIdx.y;
    int p = blockIdx.x * 256 + threadIdx.x;
    int i = p >> 8, j = p & 255;
    float f[5];
    f[0] = x[(b*CIN + 0)*NPIX0 + p];
    f[1] = x[(b*CIN + 1)*NPIX0 + p];
    f[2] = x[(b*CIN + 2)*NPIX0 + p];
    f[3] = (float)i * (1.0f/255.0f);
    f[4] = (float)j * (1.0f/255.0f);
    float h[32];
    #pragma unroll
    for (int c1 = 0; c1 < 32; c1++) {
        float v = sb1[c1];
        #pragma unroll
        for (int q = 0; q < 5; q++) v = fmaf(sw1[c1*5+q], f[q], v);
        h[c1] = gelu_exact(v);
    }
    int base = b*NC*NP + i*HP + j;
    for (int c2 = 0; c2 < 64; c2++) {
        float v = sb2[c2];
        #pragma unroll
        for (int c1 = 0; c1 < 32; c1++) v = fmaf(sw2[c2*32+c1], h[c1], v);
        g_x[base + c2*NP] = v;
    }
}

// ---------------- fused local branch, f32x2 GEMMs ---------------------------
__global__ void __launch_bounds__(128, 2) k_local(
    const float* __restrict__ in, float* __restrict__ out,
    const float* __restrict__ WfT, const float* __restrict__ Bf,
    const float* __restrict__ W3T, const float* __restrict__ B3)
{
    extern __shared__ __align__(16) float sm_local[];
    float* sX = sm_local;           // 64x64
    float* sT = sm_local + 4096;    // 128x64
    float* sW = sm_local + 12288;   // 8192 floats
    const int tid = threadIdx.x;
    const int ty = tid >> 4, tx = tid & 15;   // 8 x 16
    const int r0 = ty * 8, x0 = tx * 4;
    const int base = blockIdx.y * (NC*NP) + blockIdx.x * 64;

    #pragma unroll
    for (int i = 0; i < 32; i++) {
        int idx = tid + i*128;
        sX[idx] = in[base + (idx >> 6)*NP + (idx & 63)];
    }
    #pragma unroll
    for (int i = 0; i < 64; i++) {
        int idx = tid + i*128;
        sW[idx] = WfT[idx];
    }
    __syncthreads();

    // ---- stage A: T = gelu(Wf X + bf), 128 rows in 2 halves (K=64)
    #pragma unroll
    for (int h = 0; h < 2; h++) {
        u64 acc2[4][4];
        #pragma unroll
        for (int ip = 0; ip < 4; ip++) {
            u64 bp = pk(__ldg(&Bf[h*64 + r0 + 2*ip]), __ldg(&Bf[h*64 + r0 + 2*ip + 1]));
            #pragma unroll
            for (int j = 0; j < 4; j++) acc2[ip][j] = bp;
        }
        for (int k = 0; k < 64; k++) {
            const u64* wrow = (const u64*)(sW + k*128 + h*64 + r0);
            u64 a0 = wrow[0], a1 = wrow[1], a2 = wrow[2], a3 = wrow[3];
            float4 b = *(const float4*)&sX[k*64 + x0];
            u64 b2v[4] = {pkdup(b.x), pkdup(b.y), pkdup(b.z), pkdup(b.w)};
            #pragma unroll
            for (int j = 0; j < 4; j++) {
                acc2[0][j] = f2fma(a0, b2v[j], acc2[0][j]);
                acc2[1][j] = f2fma(a1, b2v[j], acc2[1][j]);
                acc2[2][j] = f2fma(a2, b2v[j], acc2[2][j]);
                acc2[3][j] = f2fma(a3, b2v[j], acc2[3][j]);
            }
        }
        #pragma unroll
        for (int ip = 0; ip < 4; ip++) {
            float2 v0 = up(acc2[ip][0]), v1 = up(acc2[ip][1]);
            float2 v2 = up(acc2[ip][2]), v3 = up(acc2[ip][3]);
            *(float4*)&sT[(h*64 + r0 + 2*ip    )*64 + x0] =
                make_float4(gelu_exact(v0.x), gelu_exact(v1.x), gelu_exact(v2.x), gelu_exact(v3.x));
            *(float4*)&sT[(h*64 + r0 + 2*ip + 1)*64 + x0] =
                make_float4(gelu_exact(v0.y), gelu_exact(v1.y), gelu_exact(v2.y), gelu_exact(v3.y));
        }
    }
    __syncthreads();

    #pragma unroll
    for (int i = 0; i < 64; i++) {
        int idx = tid + i*128;
        sW[idx] = W3T[idx];
    }
    __syncthreads();

    // ---- stage B: OUT = W3 T + b3 (K=128)
    {
        u64 acc2[4][4];
        #pragma unroll
        for (int ip = 0; ip < 4; ip++) {
            u64 bp = pk(__ldg(&B3[r0 + 2*ip]), __ldg(&B3[r0 + 2*ip + 1]));
            #pragma unroll
            for (int j = 0; j < 4; j++) acc2[ip][j] = bp;
        }
        for (int k = 0; k < 128; k++) {
            const u64* wrow = (const u64*)(sW + k*64 + r0);
            u64 a0 = wrow[0], a1 = wrow[1], a2 = wrow[2], a3 = wrow[3];
            float4 b = *(const float4*)&sT[k*64 + x0];
            u64 b2v[4] = {pkdup(b.x), pkdup(b.y), pkdup(b.z), pkdup(b.w)};
            #pragma unroll
            for (int j = 0; j < 4; j++) {
                acc2[0][j] = f2fma(a0, b2v[j], acc2[0][j]);
                acc2[1][j] = f2fma(a1, b2v[j], acc2[1][j]);
                acc2[2][j] = f2fma(a2, b2v[j], acc2[2][j]);
                acc2[3][j] = f2fma(a3, b2v[j], acc2[3][j]);
            }
        }
        #pragma unroll
        for (int ip = 0; ip < 4; ip++) {
            float2 v0 = up(acc2[ip][0]), v1 = up(acc2[ip][1]);
            float2 v2 = up(acc2[ip][2]), v3 = up(acc2[ip][3]);
            *(float4*)&out[base + (r0 + 2*ip    )*NP + x0] = make_float4(v0.x, v1.x, v2.x, v3.x);
            *(float4*)&out[base + (r0 + 2*ip + 1)*NP + x0] = make_float4(v0.y, v1.y, v2.y, v3.y);
        }
    }
}

// ---------------- S1: row DFT, y-pair symmetry, (re,im) f32x2 pairs ---------
__global__ void __launch_bounds__(264, 2) k_dft_rows() {
    extern __shared__ __align__(16) float2 fy_s[];   // 33 x 264
    const int bc = blockIdx.x;
    const int tid = threadIdx.x;
    for (int idx = tid; idx < 33*HP; idx += 264) {
        int m = idx / HP, y = idx % HP;
        float2 f;
        if (m < 32) f = g_Fy[m*HP + y];
        else { f = g_Fy[32*HP + y]; f.y = -f.y; }
        fy_s[idx] = f;
    }
    __syncthreads();
    const int xt = tid % 66, rq = tid / 66;
    const int x0 = xt * 4, m0 = rq * 8;
    const float* img = g_x + bc*NP;
    u64 acc2[9][4];   // (ar, ai) pairs
    #pragma unroll
    for (int r = 0; r < 9; r++)
        #pragma unroll
        for (int j = 0; j < 4; j++) acc2[r][j] = 0ULL;

    float4 va = __ldg((const float4*)(img + HP + x0));
    float4 vb = __ldg((const float4*)(img + 263*HP + x0));
    for (int y = 1; y <= 131; y++) {
        float4 na = va, nb = vb;
        if (y < 131) {
            na = __ldg((const float4*)(img + (y+1)*HP + x0));
            nb = __ldg((const float4*)(img + (263-y)*HP + x0));
        }
        u64 pd[4] = { pk(va.x+vb.x, va.x-vb.x), pk(va.y+vb.y, va.y-vb.y),
                      pk(va.z+vb.z, va.z-vb.z), pk(va.w+vb.w, va.w-vb.w) };
        #pragma unroll
        for (int r = 0; r < 9; r++) {
            u64 f2 = *(const u64*)&fy_s[(m0 + r)*HP + y];
            #pragma unroll
            for (int j = 0; j < 4; j++)
                acc2[r][j] = f2fma(pd[j], f2, acc2[r][j]);
        }
        va = na; vb = nb;
    }
    // singles y=0 (cos=1,sin=0) and y=132 (sin=0) -> re lane only
    {
        float4 v0   = __ldg((const float4*)(img + x0));
        float4 v132 = __ldg((const float4*)(img + 132*HP + x0));
        u64 z0[4] = {pk(v0.x,0.f),  pk(v0.y,0.f),  pk(v0.z,0.f),  pk(v0.w,0.f)};
        u64 z1[4] = {pk(v132.x,0.f),pk(v132.y,0.f),pk(v132.z,0.f),pk(v132.w,0.f)};
        #pragma unroll
        for (int r = 0; r < 9; r++) {
            u64 c132 = pkdup(fy_s[(m0 + r)*HP + 132].x);
            #pragma unroll
            for (int j = 0; j < 4; j++)
                acc2[r][j] = f2fma(z1[j], c132, f2add(acc2[r][j], z0[j]));
        }
    }
    #pragma unroll
    for (int r = 0; r < 9; r++) {
        int m = m0 + r;
        u64* dst = (u64*)&g_T1[(bc*33 + m)*HP + x0];
        #pragma unroll
        for (int j = 0; j < 4; j++) dst[j] = acc2[r][j];
    }
}

// ---------------- S2: col DFT, cross-sums as f32x2 pairs --------------------
__global__ void __launch_bounds__(256) k_dft_cols() {
    extern __shared__ __align__(16) float2 t1s[];   // 33 x 264
    const int bc = blockIdx.x;
    const int tid = threadIdx.x;
    for (int idx = tid; idx < 33*HP; idx += 256)
        t1s[idx] = g_T1[bc*(33*HP) + idx];
    __syncthreads();
    const int k = tid & 31, rq = tid >> 5;
    u64 P1[4] = {0,0,0,0};   // (Sxx, Syx)
    u64 P2[4] = {0,0,0,0};   // (Sxy, Syy)
    u64 T1v = 0, T2v = 0;
    for (int x = 0; x < HP; x++) {
        float2 f = __ldg(&g_FxT[x*NM + k]);
        u64 fx = pkdup(f.x), fy = pkdup(f.y);
        #pragma unroll
        for (int j = 0; j < 4; j++) {
            u64 pv = *(const u64*)&t1s[(rq + 8*j)*HP + x];
            P1[j] = f2fma(pv, fx, P1[j]);
            P2[j] = f2fma(pv, fy, P2[j]);
        }
        if (rq == 0) {
            u64 pv = *(const u64*)&t1s[32*HP + x];
            T1v = f2fma(pv, fx, T1v);
            T2v = f2fma(pv, fy, T2v);
        }
    }
    #pragma unroll
    for (int j = 0; j < 4; j++) {
        int m = rq + 8*j;
        float2 a = up(P1[j]);   // (Sxx, Syx)
        float2 b = up(P2[j]);   // (Sxy, Syy)
        g_xf[(bc*NR + m)*NM + k] = make_float2(a.x - b.y, b.x + a.y);
        if (m >= 1)
            g_xf[(bc*NR + (64 - m))*NM + k] = make_float2(a.x + b.y, b.x - a.y);
    }
    if (rq == 0) {
        float2 a = up(T1v);
        float2 b = up(T2v);
        g_xf[(bc*NR + 32)*NM + k] = make_float2(a.x + b.y, b.x - a.y);
    }
}

// ---------------- S3: channel mix (unchanged) --------------------------------
__global__ void __launch_bounds__(256) k_chanmix(
    const float* __restrict__ w1r, const float* __restrict__ w1i,
    const float* __restrict__ w2r, const float* __restrict__ w2i)
{
    extern __shared__ __align__(16) float2 xs[];   // 4*64*32
    const int r = blockIdx.y, oh = blockIdx.x;
    const float* wr; const float* wi; int m1;
    if (r < 32) { wr = w1r; wi = w1i; m1 = r; }
    else        { wr = w2r; wi = w2i; m1 = r - 32; }
    const int tid = threadIdx.x;
    for (int idx = tid; idx < NB*NC*NM; idx += 256) {
        int b = idx >> 11, i = (idx >> 5) & 63, kk = idx & 31;
        xs[idx] = g_xf[((b*NC + i)*NR + r)*NM + kk];
    }
    __syncthreads();
    const int k = tid & 31, og = tid >> 5;
    const int o0 = oh*16 + og*2;
    const int woff = m1*NM + k;
    float ar[2][4], ai[2][4];
    #pragma unroll
    for (int oo = 0; oo < 2; oo++)
        #pragma unroll
        for (int b = 0; b < 4; b++) { ar[oo][b] = 0.f; ai[oo][b] = 0.f; }
    #pragma unroll 2
    for (int i = 0; i < NC; i++) {
        float wre0 = __ldg(&wr[(i*64 + o0    )*1024 + woff]);
        float wim0 = __ldg(&wi[(i*64 + o0    )*1024 + woff]);
        float wre1 = __ldg(&wr[(i*64 + o0 + 1)*1024 + woff]);
        float wim1 = __ldg(&wi[(i*64 + o0 + 1)*1024 + woff]);
        #pragma unroll
        for (int b = 0; b < 4; b++) {
            float2 xv = xs[(b*NC + i)*NM + k];
            ar[0][b] = fmaf(xv.x, wre0, fmaf(-xv.y, wim0, ar[0][b]));
            ai[0][b] = fmaf(xv.x, wim0, fmaf( xv.y, wre0, ai[0][b]));
            ar[1][b] = fmaf(xv.x, wre1, fmaf(-xv.y, wim1, ar[1][b]));
            ai[1][b] = fmaf(xv.x, wim1, fmaf( xv.y, wre1, ai[1][b]));
        }
    }
    #pragma unroll
    for (int oo = 0; oo < 2; oo++)
        #pragma unroll
        for (int b = 0; b < 4; b++)
            g_of[((b*NC + o0 + oo)*NR + r)*NM + k] = make_float2(ar[oo][b], ai[oo][b]);
}

// ---------------- fused inverse, pair symmetry + f32x2 ----------------------
template<bool LAST>
__global__ void __launch_bounds__(272) k_inv(float* __restrict__ out) {
    extern __shared__ __align__(16) float2 sm_inv[];
    float2* os = sm_inv;            // 64*32 -> pair-transformed in place
    float2* Us = sm_inv + 2048;     // 264*32
    const int bo = blockIdx.x;
    const int tid = threadIdx.x;
    for (int idx = tid; idx < 2048; idx += 272)
        os[idx] = g_of[bo*2048 + idx];
    __syncthreads();
    for (int idx = tid; idx < 31*32; idx += 272) {
        int m = (idx >> 5) + 1, k = idx & 31;
        float2 A = os[m*NM + k], B = os[(64 - m)*NM + k];
        os[m*NM + k]        = make_float2(A.x + B.x, A.y - B.y);   // (P.x, Q.y)
        os[(64 - m)*NM + k] = make_float2(A.y + B.y, A.x - B.x);   // (P.y, Q.x)
    }
    __syncthreads();

    // ---- phase A: U[y,k]  (y-pairs via split cos/sin tables)
    if (tid < 256) {
        const int k = tid & 31, yq = tid >> 5;
        const float2 o0  = os[k];
        const float2 o32 = os[32*NM + k];
        const u64 o0x = pkdup(o0.x), o0y = pkdup(o0.y);
        const u64 p32x = pkdup(o32.x), p32y = pkdup(o32.y), n32y = pkdup(-o32.y);
        for (int it = 0; it < 9; it++) {
            int yg = yq + it*8;
            if (yg >= 66) break;
            int y0 = yg * 4;
            ulonglong2 C32 = __ldg((const ulonglong2*)&g_Fyc[32*HP + y0]);
            ulonglong2 S32 = __ldg((const ulonglong2*)&g_Fys[32*HP + y0]);
            // re = o0.x + o32.x*c - o32.y*s ; im = o0.y + o32.y*c + o32.x*s
            u64 R01 = f2fma(p32x, C32.x, f2fma(n32y, S32.x, o0x));
            u64 R23 = f2fma(p32x, C32.y, f2fma(n32y, S32.y, o0x));
            u64 I01 = f2fma(p32y, C32.x, f2fma(p32x, S32.x, o0y));
            u64 I23 = f2fma(p32y, C32.y, f2fma(p32x, S32.y, o0y));
            #pragma unroll 4
            for (int m = 1; m <= 31; m++) {
                float2 Ps = os[m*NM + k];          // (P.x, Q.y)
                float2 Qs = os[(64 - m)*NM + k];   // (P.y, Q.x)
                ulonglong2 C = __ldg((const ulonglong2*)&g_Fyc[m*HP + y0]);
                ulonglong2 S = __ldg((const ulonglong2*)&g_Fys[m*HP + y0]);
                u64 px_ = pkdup(Ps.x), py_ = pkdup(Ps.y);
                u64 qx_ = pkdup(Qs.x), qy_ = pkdup(-Qs.y);
                // re += Ps.x*c + Ps.y*s ; im += Qs.x*c - Qs.y*s
                R01 = f2fma(px_, C.x, f2fma(py_, S.x, R01));
                R23 = f2fma(px_, C.y, f2fma(py_, S.y, R23));
                I01 = f2fma(qx_, C.x, f2fma(qy_, S.x, I01));
                I23 = f2fma(qx_, C.y, f2fma(qy_, S.y, I23));
            }
            float2 r01 = up(R01), r23 = up(R23), i01 = up(I01), i23 = up(I23);
            Us[(y0+0)*NM + k] = make_float2(r01.x*INV_HP, i01.x*INV_HP);
            Us[(y0+1)*NM + k] = make_float2(r01.y*INV_HP, i01.y*INV_HP);
            Us[(y0+2)*NM + k] = make_float2(r23.x*INV_HP, i23.x*INV_HP);
            Us[(y0+3)*NM + k] = make_float2(r23.y*INV_HP, i23.y*INV_HP);
        }
    }
    __syncthreads();

    // ---- phase B: (E,O) f32x2 pairs — zero packing
    const int xt = tid % 34, yq2 = tid / 34;
    const int x0 = xt * 4;
    for (int p = 0; p < 9; p++) {
        int ybase = p*32 + yq2*4;
        if (p == 8 && yq2 >= 2) break;
        u64 EO[4][4];
        float u0[4];
        #pragma unroll
        for (int j = 0; j < 4; j++) {
            u0[j] = Us[(ybase + j)*NM].x;
            #pragma unroll
            for (int q = 0; q < 4; q++) EO[j][q] = 0ULL;
        }
        for (int k = 1; k < NM; k++) {
            const ulonglong2* fp = (const ulonglong2*)&g_Fx[k*HP + x0];
            ulonglong2 wA = __ldg(fp);
            ulonglong2 wB = __ldg(fp + 1);
            #pragma unroll
            for (int j = 0; j < 4; j++) {
                u64 u = *(const u64*)&Us[(ybase + j)*NM + k];
                EO[j][0] = f2fma(u, wA.x, EO[j][0]);
                EO[j][1] = f2fma(u, wA.y, EO[j][1]);
                EO[j][2] = f2fma(u, wB.x, EO[j][2]);
                EO[j][3] = f2fma(u, wB.y, EO[j][3]);
            }
        }
        #pragma unroll
        for (int j = 0; j < 4; j++) {
            int y = ybase + j;
            float2 eo[4] = {up(EO[j][0]), up(EO[j][1]), up(EO[j][2]), up(EO[j][3])};
            if (xt < 33) {
                int idx = bo*NP + y*HP + x0;
                float4 h = *(const float4*)&g_hbr[idx];
                float4 rv = make_float4(
                    h.x + (u0[j] + 2.f*(eo[0].x + eo[0].y))*INV_HP,
                    h.y + (u0[j] + 2.f*(eo[1].x + eo[1].y))*INV_HP,
                    h.z + (u0[j] + 2.f*(eo[2].x + eo[2].y))*INV_HP,
                    h.w + (u0[j] + 2.f*(eo[3].x + eo[3].y))*INV_HP);
                if (LAST) { if (y < H0) *(float4*)&out[bo*NPIX0 + y*W0 + x0] = rv; }
                else      *(float4*)&g_x[idx] = rv;
                #pragma unroll
                for (int q = 0; q < 4; q++) {
                    if (xt == 0 && q == 0) continue;
                    int xm = 264 - (x0 + q);
                    float hm = __ldg(&g_hbr[bo*NP + y*HP + xm]);
                    float vm = hm + (u0[j] + 2.f*(eo[q].x - eo[q].y))*INV_HP;
                    if (LAST) { if (y < H0 && xm < W0) out[bo*NPIX0 + y*W0 + xm] = vm; }
                    else      g_x[bo*NP + y*HP + xm] = vm;
                }
            } else {   // x = 132 (self-mirror)
                int idx = bo*NP + y*HP + 132;
                float hm = __ldg(&g_hbr[idx]);
                float vm = hm + (u0[j] + 2.f*(eo[0].x + eo[0].y))*INV_HP;
                if (LAST) { if (y < H0) out[bo*NPIX0 + y*W0 + 132] = vm; }
                else      g_x[idx] = vm;
            }
        }
    }
}

// ---------------- launch -----------------------------------------------------
extern "C" void kernel_launch(void* const* d_in, const int* in_sizes, int n_in,
                              void* d_out, int out_size)
{
    const float* x   = (const float*)d_in[0];
    const float* lw1 = (const float*)d_in[1];
    const float* lb1 = (const float*)d_in[2];
    const float* lw2 = (const float*)d_in[3];
    const float* lb2 = (const float*)d_in[4];
    const float* cw  = (const float*)d_in[5];
    const float* cb  = (const float*)d_in[6];
    const float* m1w = (const float*)d_in[7];
    const float* m1b = (const float*)d_in[8];
    const float* m2w = (const float*)d_in[9];
    const float* m2b = (const float*)d_in[10];
    const float* s1r = (const float*)d_in[11];
    const float* s1i = (const float*)d_in[12];
    const float* s2r = (const float*)d_in[13];
    const float* s2i = (const float*)d_in[14];
    float* out = (float*)d_out;

    float *px, *ph, *pwf, *pw3, *pbf;
    cudaGetSymbolAddress((void**)&px,  g_x);
    cudaGetSymbolAddress((void**)&ph,  g_hbr);
    cudaGetSymbolAddress((void**)&pwf, g_WfT);
    cudaGetSymbolAddress((void**)&pw3, g_W3T);
    cudaGetSymbolAddress((void**)&pbf, g_bf);

    const int LOCAL_SMEM = 20480 * 4;            // 81920 B
    const int DFTR_SMEM  = 33 * HP * 8;          // 69696 B
    const int DFTC_SMEM  = 33 * HP * 8;          // 69696 B
    const int CMIX_SMEM  = NB*NC*NM * 8;         // 65536 B
    const int INV_SMEM   = (NR*NM + HP*NM) * 8;  // 83968 B
    cudaFuncSetAttribute(k_local,      cudaFuncAttributeMaxDynamicSharedMemorySize, LOCAL_SMEM);
    cudaFuncSetAttribute(k_dft_rows,   cudaFuncAttributeMaxDynamicSharedMemorySize, DFTR_SMEM);
    cudaFuncSetAttribute(k_dft_cols,   cudaFuncAttributeMaxDynamicSharedMemorySize, DFTC_SMEM);
    cudaFuncSetAttribute(k_chanmix,    cudaFuncAttributeMaxDynamicSharedMemorySize, CMIX_SMEM);
    cudaFuncSetAttribute(k_inv<false>, cudaFuncAttributeMaxDynamicSharedMemorySize, INV_SMEM);
    cudaFuncSetAttribute(k_inv<true >, cudaFuncAttributeMaxDynamicSharedMemorySize, INV_SMEM);

    k_tables<<<132, 256>>>();
    k_wfuse<<<194, 256>>>(cw, cb, m1w, m1b, m2w);
    k_zero_x<<<4096, 256>>>();
    k_lift<<<dim3(256, NB), 256>>>(x, lw1, lb1, lw2, lb2);

    for (int L = 0; L < 3; L++) {
        k_local<<<dim3(NP/64, NB), 128, LOCAL_SMEM>>>(
            px, ph, pwf + L*8192, pbf + L*128, pw3 + L*8192, m2b + L*64);
        k_dft_rows<<<NB*NC, 264, DFTR_SMEM>>>();
        k_dft_cols<<<NB*NC, 256, DFTC_SMEM>>>();
        k_chanmix<<<dim3(4, 64), 256, CMIX_SMEM>>>(s1r + L*SPW, s1i + L*SPW, s2r + L*SPW, s2i + L*SPW);
        if (L < 2) k_inv<false><<<NB*NC, 272, INV_SMEM>>>(out);
        else       k_inv<true ><<<NB*NC, 272, INV_SMEM>>>(out);
    }
}

// round 9
// speedup vs baseline: 2.5312x; 1.0403x over previous
#include <cuda_runtime.h>
#include <math.h>

#define NB 4
#define CIN 3
#define NC 64
#define H0 256
#define W0 256
#define NPIX0 (H0*W0)
#define HP 264
#define NP (HP*HP)      /* 69696 */
#define NR 64
#define NM 32
#define SPW (64*64*32*32)
#define INV_HP (1.0f/264.0f)

typedef unsigned long long u64;

// ---------------- f32x2 packed-FMA helpers -----------------------------------
__device__ __forceinline__ u64 pk(float lo, float hi) {
    u64 r; asm("mov.b64 %0, {%1, %2};" : "=l"(r) : "f"(lo), "f"(hi)); return r;
}
__device__ __forceinline__ u64 pkdup(float v) { return pk(v, v); }
__device__ __forceinline__ float2 up(u64 v) {
    float lo, hi; asm("mov.b64 {%0, %1}, %2;" : "=f"(lo), "=f"(hi) : "l"(v));
    return make_float2(lo, hi);
}
__device__ __forceinline__ u64 f2fma(u64 a, u64 b, u64 c) {
    u64 d; asm("fma.rn.f32x2 %0, %1, %2, %3;" : "=l"(d) : "l"(a), "l"(b), "l"(c)); return d;
}
__device__ __forceinline__ u64 f2add(u64 a, u64 b) {
    u64 d; asm("add.rn.f32x2 %0, %1, %2;" : "=l"(d) : "l"(a), "l"(b)); return d;
}

// ---------------- scratch ----------------------------------------------------
__device__ float  g_x  [NB*NC*NP];
__device__ float  g_hbr[NB*NC*NP];
__device__ float2 g_T1 [NB*NC*33*HP];
__device__ float2 g_xf [NB*NC*NR*NM];
__device__ float2 g_of [NB*NC*NR*NM];
__device__ float2 g_Fy [NR*HP];
__device__ float2 g_Fx [NM*HP];
__device__ float2 g_FxT[HP*NM];
__device__ float  g_Fyc[33*HP];
__device__ float  g_Fys[33*HP];
__device__ float  g_WfT[3*64*128];
__device__ float  g_W3T[3*128*64];
__device__ float  g_bf [3*128];

__device__ __forceinline__ float gelu_exact(float v) {
    return 0.5f * v * (1.0f + erff(v * 0.70710678118654752440f));
}

// ---------------- init --------------------------------------------------------
__global__ void k_tables() {
    int idx = blockIdx.x * 256 + threadIdx.x;
    if (idx < NR*HP) {
        int r = idx / HP, y = idx % HP;
        int ky = (r < 32) ? r : r + 200;
        int m = (ky * y) % HP;
        double a = 6.283185307179586 * (double)m / (double)HP;
        float2 f = make_float2((float)cos(a), (float)(-sin(a)));
        g_Fy[idx] = f;
        if (r <= 32) { g_Fyc[r*HP + y] = f.x; g_Fys[r*HP + y] = f.y; }
    } else if (idx < NR*HP + NM*HP) {
        int j = idx - NR*HP;
        int k = j / HP, xx = j % HP;
        int m = (k * xx) % HP;
        double a = 6.283185307179586 * (double)m / (double)HP;
        float2 f = make_float2((float)cos(a), (float)(-sin(a)));
        g_Fx[j] = f;
        g_FxT[xx*NM + k] = f;
    }
}

__global__ void k_wfuse(const float* __restrict__ cw,  const float* __restrict__ cb,
                        const float* __restrict__ m1w, const float* __restrict__ m1b,
                        const float* __restrict__ m2w) {
    int idx = blockIdx.x * 256 + threadIdx.x;
    if (idx < 3*8192) {
        int L = idx / 8192, r = idx % 8192, k = r >> 7, o = r & 127;
        const float* W2 = m1w + L*8192;
        const float* W1 = cw  + L*4096;
        double s = 0.0;
        for (int j = 0; j < 64; j++) s += (double)W2[o*64 + j] * (double)W1[j*64 + k];
        g_WfT[idx] = (float)s;
    } else if (idx < 6*8192) {
        int i = idx - 3*8192;
        int L = i / 8192, r = i % 8192, k = r >> 6, o = r & 63;
        g_W3T[i] = m2w[L*8192 + o*128 + k];
    } else if (idx < 6*8192 + 384) {
        int i = idx - 6*8192;
        int L = i / 128, o = i % 128;
        const float* W2 = m1w + L*8192;
        double s = (double)m1b[L*128 + o];
        for (int j = 0; j < 64; j++) s += (double)W2[o*64 + j] * (double)cb[L*64 + j];
        g_bf[i] = (float)s;
    }
}

// zero only the right/bottom padding bands (lift fills the 256x256 interior)
__global__ void k_zero_pad() {
    int idx = blockIdx.x * 256 + threadIdx.x;   // 256 images x 4160 px
    int img = idx / 4160, r = idx % 4160;
    int row, col;
    if (r < 2048) { row = r >> 3; col = 256 + (r & 7); }
    else          { int rr = r - 2048; row = 256 + rr / HP; col = rr % HP; }
    g_x[img*NP + row*HP + col] = 0.0f;
}

// ---------------- lift: 5 -> 32 (GELU) -> 64, second GEMM f32x2 -------------
__global__ void __launch_bounds__(256) k_lift(
    const float* __restrict__ x,
    const float* __restrict__ w1, const float* __restrict__ b1,
    const float* __restrict__ w2, const float* __restrict__ b2)
{
    __shared__ float sw1[32*5], sb1[32], sb2[64];
    __shared__ __align__(16) float sw2T[32*64];   // [c1][c2]
    for (int i = threadIdx.x; i < 160;  i += 256) sw1[i] = w1[i];
    for (int i = threadIdx.x; i < 32;   i += 256) sb1[i] = b1[i];
    for (int i = threadIdx.x; i < 2048; i += 256) sw2T[(i & 31)*64 + (i >> 5)] = w2[i];
    for (int i = threadIdx.x; i < 64;   i += 256) sb2[i] = b2[i];
    __syncthreads();
    int b = blockIdx.y;
    int p = blockIdx.x * 256 + threadIdx.x;
    int i = p >> 8, j = p & 255;
    float f[5];
    f[0] = x[(b*CIN + 0)*NPIX0 + p];
    f[1] = x[(b*CIN + 1)*NPIX0 + p];
    f[2] = x[(b*CIN + 2)*NPIX0 + p];
    f[3] = (float)i * (1.0f/255.0f);
    f[4] = (float)j * (1.0f/255.0f);
    float h[32];
    #pragma unroll
    for (int c1 = 0; c1 < 32; c1++) {
        float v = sb1[c1];
        #pragma unroll
        for (int q = 0; q < 5; q++) v = fmaf(sw1[c1*5+q], f[q], v);
        h[c1] = gelu_exact(v);
    }
    u64 acc[32];
    #pragma unroll
    for (int o = 0; o < 32; o++) acc[o] = pk(sb2[2*o], sb2[2*o+1]);
    #pragma unroll
    for (int c1 = 0; c1 < 32; c1++) {
        u64 hd = pkdup(h[c1]);
        const u64* wrow = (const u64*)&sw2T[c1*64];
        #pragma unroll
        for (int o = 0; o < 32; o++) acc[o] = f2fma(hd, wrow[o], acc[o]);
    }
    int base = b*NC*NP + i*HP + j;
    #pragma unroll
    for (int o = 0; o < 32; o++) {
        float2 v = up(acc[o]);
        g_x[base + (2*o  )*NP] = v.x;
        g_x[base + (2*o+1)*NP] = v.y;
    }
}

// ---------------- fused local branch, f32x2 GEMMs (unchanged) ---------------
__global__ void __launch_bounds__(128, 2) k_local(
    const float* __restrict__ in, float* __restrict__ out,
    const float* __restrict__ WfT, const float* __restrict__ Bf,
    const float* __restrict__ W3T, const float* __restrict__ B3)
{
    extern __shared__ __align__(16) float sm_local[];
    float* sX = sm_local;           // 64x64
    float* sT = sm_local + 4096;    // 128x64
    float* sW = sm_local + 12288;   // 8192 floats
    const int tid = threadIdx.x;
    const int ty = tid >> 4, tx = tid & 15;
    const int r0 = ty * 8, x0 = tx * 4;
    const int base = blockIdx.y * (NC*NP) + blockIdx.x * 64;

    #pragma unroll
    for (int i = 0; i < 32; i++) {
        int idx = tid + i*128;
        sX[idx] = in[base + (idx >> 6)*NP + (idx & 63)];
    }
    #pragma unroll
    for (int i = 0; i < 64; i++) {
        int idx = tid + i*128;
        sW[idx] = WfT[idx];
    }
    __syncthreads();

    #pragma unroll
    for (int h = 0; h < 2; h++) {
        u64 acc2[4][4];
        #pragma unroll
        for (int ip = 0; ip < 4; ip++) {
            u64 bp = pk(__ldg(&Bf[h*64 + r0 + 2*ip]), __ldg(&Bf[h*64 + r0 + 2*ip + 1]));
            #pragma unroll
            for (int j = 0; j < 4; j++) acc2[ip][j] = bp;
        }
        for (int k = 0; k < 64; k++) {
            const u64* wrow = (const u64*)(sW + k*128 + h*64 + r0);
            u64 a0 = wrow[0], a1 = wrow[1], a2 = wrow[2], a3 = wrow[3];
            float4 b = *(const float4*)&sX[k*64 + x0];
            u64 b2v[4] = {pkdup(b.x), pkdup(b.y), pkdup(b.z), pkdup(b.w)};
            #pragma unroll
            for (int j = 0; j < 4; j++) {
                acc2[0][j] = f2fma(a0, b2v[j], acc2[0][j]);
                acc2[1][j] = f2fma(a1, b2v[j], acc2[1][j]);
                acc2[2][j] = f2fma(a2, b2v[j], acc2[2][j]);
                acc2[3][j] = f2fma(a3, b2v[j], acc2[3][j]);
            }
        }
        #pragma unroll
        for (int ip = 0; ip < 4; ip++) {
            float2 v0 = up(acc2[ip][0]), v1 = up(acc2[ip][1]);
            float2 v2 = up(acc2[ip][2]), v3 = up(acc2[ip][3]);
            *(float4*)&sT[(h*64 + r0 + 2*ip    )*64 + x0] =
                make_float4(gelu_exact(v0.x), gelu_exact(v1.x), gelu_exact(v2.x), gelu_exact(v3.x));
            *(float4*)&sT[(h*64 + r0 + 2*ip + 1)*64 + x0] =
                make_float4(gelu_exact(v0.y), gelu_exact(v1.y), gelu_exact(v2.y), gelu_exact(v3.y));
        }
    }
    __syncthreads();

    #pragma unroll
    for (int i = 0; i < 64; i++) {
        int idx = tid + i*128;
        sW[idx] = W3T[idx];
    }
    __syncthreads();

    {
        u64 acc2[4][4];
        #pragma unroll
        for (int ip = 0; ip < 4; ip++) {
            u64 bp = pk(__ldg(&B3[r0 + 2*ip]), __ldg(&B3[r0 + 2*ip + 1]));
            #pragma unroll
            for (int j = 0; j < 4; j++) acc2[ip][j] = bp;
        }
        for (int k = 0; k < 128; k++) {
            const u64* wrow = (const u64*)(sW + k*64 + r0);
            u64 a0 = wrow[0], a1 = wrow[1], a2 = wrow[2], a3 = wrow[3];
            float4 b = *(const float4*)&sT[k*64 + x0];
            u64 b2v[4] = {pkdup(b.x), pkdup(b.y), pkdup(b.z), pkdup(b.w)};
            #pragma unroll
            for (int j = 0; j < 4; j++) {
                acc2[0][j] = f2fma(a0, b2v[j], acc2[0][j]);
                acc2[1][j] = f2fma(a1, b2v[j], acc2[1][j]);
                acc2[2][j] = f2fma(a2, b2v[j], acc2[2][j]);
                acc2[3][j] = f2fma(a3, b2v[j], acc2[3][j]);
            }
        }
        #pragma unroll
        for (int ip = 0; ip < 4; ip++) {
            float2 v0 = up(acc2[ip][0]), v1 = up(acc2[ip][1]);
            float2 v2 = up(acc2[ip][2]), v3 = up(acc2[ip][3]);
            *(float4*)&out[base + (r0 + 2*ip    )*NP + x0] = make_float4(v0.x, v1.x, v2.x, v3.x);
            *(float4*)&out[base + (r0 + 2*ip + 1)*NP + x0] = make_float4(v0.y, v1.y, v2.y, v3.y);
        }
    }
}

// ---------------- S1: row DFT, 2 mode-groups per bc --------------------------
// grid (bc, 2); block 264; modes m_base..m_base+16 (m=16 dup across groups)
__global__ void __launch_bounds__(264) k_dft_rows() {
    extern __shared__ __align__(16) float2 fy_s[];   // 17 x 264
    const int bc = blockIdx.x, mgrp = blockIdx.y;
    const int m_base = mgrp * 16;
    const int tid = threadIdx.x;
    for (int idx = tid; idx < 17*HP; idx += 264) {
        int ml = idx / HP, y = idx % HP;
        int m = m_base + ml;
        float2 f;
        if (m < 32) f = g_Fy[m*HP + y];
        else { f = g_Fy[32*HP + y]; f.y = -f.y; }
        fy_s[idx] = f;
    }
    __syncthreads();
    const int xt = tid % 66, rq = tid / 66;
    const int x0 = xt * 4, ml0 = rq * 4;
    const bool five = (rq == 3);     // rq3 covers local modes 12..16
    const float* img = g_x + bc*NP;
    u64 acc2[5][4];
    #pragma unroll
    for (int r = 0; r < 5; r++)
        #pragma unroll
        for (int j = 0; j < 4; j++) acc2[r][j] = 0ULL;

    float4 va = __ldg((const float4*)(img + HP + x0));
    float4 vb = __ldg((const float4*)(img + 263*HP + x0));
    for (int y = 1; y <= 131; y++) {
        float4 na = va, nb = vb;
        if (y < 131) {
            na = __ldg((const float4*)(img + (y+1)*HP + x0));
            nb = __ldg((const float4*)(img + (263-y)*HP + x0));
        }
        u64 pd[4] = { pk(va.x+vb.x, va.x-vb.x), pk(va.y+vb.y, va.y-vb.y),
                      pk(va.z+vb.z, va.z-vb.z), pk(va.w+vb.w, va.w-vb.w) };
        #pragma unroll
        for (int r = 0; r < 4; r++) {
            u64 f2 = *(const u64*)&fy_s[(ml0 + r)*HP + y];
            #pragma unroll
            for (int j = 0; j < 4; j++)
                acc2[r][j] = f2fma(pd[j], f2, acc2[r][j]);
        }
        if (five) {
            u64 f2 = *(const u64*)&fy_s[16*HP + y];
            #pragma unroll
            for (int j = 0; j < 4; j++)
                acc2[4][j] = f2fma(pd[j], f2, acc2[4][j]);
        }
        va = na; vb = nb;
    }
    {   // singles y=0 and y=132
        float4 v0   = __ldg((const float4*)(img + x0));
        float4 v132 = __ldg((const float4*)(img + 132*HP + x0));
        u64 z0[4] = {pk(v0.x,0.f),  pk(v0.y,0.f),  pk(v0.z,0.f),  pk(v0.w,0.f)};
        u64 z1[4] = {pk(v132.x,0.f),pk(v132.y,0.f),pk(v132.z,0.f),pk(v132.w,0.f)};
        #pragma unroll
        for (int r = 0; r < 4; r++) {
            u64 c132 = pkdup(fy_s[(ml0 + r)*HP + 132].x);
            #pragma unroll
            for (int j = 0; j < 4; j++)
                acc2[r][j] = f2fma(z1[j], c132, f2add(acc2[r][j], z0[j]));
        }
        if (five) {
            u64 c132 = pkdup(fy_s[16*HP + 132].x);
            #pragma unroll
            for (int j = 0; j < 4; j++)
                acc2[4][j] = f2fma(z1[j], c132, f2add(acc2[4][j], z0[j]));
        }
    }
    #pragma unroll
    for (int r = 0; r < 4; r++) {
        int m = m_base + ml0 + r;
        u64* dst = (u64*)&g_T1[(bc*33 + m)*HP + x0];
        #pragma unroll
        for (int j = 0; j < 4; j++) dst[j] = acc2[r][j];
    }
    if (five) {
        u64* dst = (u64*)&g_T1[(bc*33 + m_base + 16)*HP + x0];
        #pragma unroll
        for (int j = 0; j < 4; j++) dst[j] = acc2[4][j];
    }
}

// ---------------- S2: col DFT, 2 row-groups per bc ---------------------------
// grid (bc, 2); by=0: rows 0..15, by=1: rows 16..31 (+32)
__global__ void __launch_bounds__(256) k_dft_cols() {
    extern __shared__ __align__(16) float2 t1s[];   // up to 17 x 264
    const int bc = blockIdx.x, by = blockIdx.y;
    const int tid = threadIdx.x;
    const int nrows = by ? 17 : 16;
    const int roff = by * 16 * HP;
    for (int idx = tid; idx < nrows*HP; idx += 256)
        t1s[idx] = g_T1[bc*(33*HP) + roff + idx];
    __syncthreads();
    const int k = tid & 31, rq = tid >> 5;
    u64 P1[2] = {0,0};   // (Sxx, Syx)
    u64 P2[2] = {0,0};   // (Sxy, Syy)
    u64 T1v = 0, T2v = 0;
    const bool do32 = (by == 1) && (rq == 0);
    for (int x = 0; x < HP; x++) {
        float2 f = __ldg(&g_FxT[x*NM + k]);
        u64 fx = pkdup(f.x), fy = pkdup(f.y);
        #pragma unroll
        for (int j = 0; j < 2; j++) {
            u64 pv = *(const u64*)&t1s[(rq + 8*j)*HP + x];
            P1[j] = f2fma(pv, fx, P1[j]);
            P2[j] = f2fma(pv, fy, P2[j]);
        }
        if (do32) {
            u64 pv = *(const u64*)&t1s[16*HP + x];
            T1v = f2fma(pv, fx, T1v);
            T2v = f2fma(pv, fy, T2v);
        }
    }
    #pragma unroll
    for (int j = 0; j < 2; j++) {
        int m = by*16 + rq + 8*j;
        float2 a = up(P1[j]);
        float2 b = up(P2[j]);
        g_xf[(bc*NR + m)*NM + k] = make_float2(a.x - b.y, b.x + a.y);
        if (m >= 1)
            g_xf[(bc*NR + (64 - m))*NM + k] = make_float2(a.x + b.y, b.x - a.y);
    }
    if (do32) {
        float2 a = up(T1v);
        float2 b = up(T2v);
        g_xf[(bc*NR + 32)*NM + k] = make_float2(a.x + b.y, b.x - a.y);
    }
}

// ---------------- S3: channel mix (unchanged) --------------------------------
__global__ void __launch_bounds__(256) k_chanmix(
    const float* __restrict__ w1r, const float* __restrict__ w1i,
    const float* __restrict__ w2r, const float* __restrict__ w2i)
{
    extern __shared__ __align__(16) float2 xs[];
    const int r = blockIdx.y, oh = blockIdx.x;
    const float* wr; const float* wi; int m1;
    if (r < 32) { wr = w1r; wi = w1i; m1 = r; }
    else        { wr = w2r; wi = w2i; m1 = r - 32; }
    const int tid = threadIdx.x;
    for (int idx = tid; idx < NB*NC*NM; idx += 256) {
        int b = idx >> 11, i = (idx >> 5) & 63, kk = idx & 31;
        xs[idx] = g_xf[((b*NC + i)*NR + r)*NM + kk];
    }
    __syncthreads();
    const int k = tid & 31, og = tid >> 5;
    const int o0 = oh*16 + og*2;
    const int woff = m1*NM + k;
    float ar[2][4], ai[2][4];
    #pragma unroll
    for (int oo = 0; oo < 2; oo++)
        #pragma unroll
        for (int b = 0; b < 4; b++) { ar[oo][b] = 0.f; ai[oo][b] = 0.f; }
    #pragma unroll 2
    for (int i = 0; i < NC; i++) {
        float wre0 = __ldg(&wr[(i*64 + o0    )*1024 + woff]);
        float wim0 = __ldg(&wi[(i*64 + o0    )*1024 + woff]);
        float wre1 = __ldg(&wr[(i*64 + o0 + 1)*1024 + woff]);
        float wim1 = __ldg(&wi[(i*64 + o0 + 1)*1024 + woff]);
        #pragma unroll
        for (int b = 0; b < 4; b++) {
            float2 xv = xs[(b*NC + i)*NM + k];
            ar[0][b] = fmaf(xv.x, wre0, fmaf(-xv.y, wim0, ar[0][b]));
            ai[0][b] = fmaf(xv.x, wim0, fmaf( xv.y, wre0, ai[0][b]));
            ar[1][b] = fmaf(xv.x, wre1, fmaf(-xv.y, wim1, ar[1][b]));
            ai[1][b] = fmaf(xv.x, wim1, fmaf( xv.y, wre1, ai[1][b]));
        }
    }
    #pragma unroll
    for (int oo = 0; oo < 2; oo++)
        #pragma unroll
        for (int b = 0; b < 4; b++)
            g_of[((b*NC + o0 + oo)*NR + r)*NM + k] = make_float2(ar[oo][b], ai[oo][b]);
}

// ---------------- fused inverse: 4 y-chunks per bc ---------------------------
// grid (bc, 4); chunks y = [0,68), [68,136), [136,200), [200,264)
template<bool LAST>
__global__ void __launch_bounds__(272) k_inv(float* __restrict__ out) {
    extern __shared__ __align__(16) float2 sm_inv[];
    float2* os = sm_inv;            // 2048
    float2* Us = sm_inv + 2048;     // up to 68*32
    const int bo = blockIdx.x, ch = blockIdx.y;
    const int ybase = ch*68 - ((ch >= 3) ? 4 : 0);   // 0,68,136,200
    const int ngrp  = (ch < 2) ? 17 : 16;            // groups of 4 y's
    const int tid = threadIdx.x;
    for (int idx = tid; idx < 2048; idx += 272)
        os[idx] = g_of[bo*2048 + idx];
    __syncthreads();
    for (int idx = tid; idx < 31*32; idx += 272) {
        int m = (idx >> 5) + 1, k = idx & 31;
        float2 A = os[m*NM + k], B = os[(64 - m)*NM + k];
        os[m*NM + k]        = make_float2(A.x + B.x, A.y - B.y);   // (P.x, Q.y)
        os[(64 - m)*NM + k] = make_float2(A.y + B.y, A.x - B.x);   // (P.y, Q.x)
    }
    __syncthreads();

    // ---- phase A
    if (tid < 256) {
        const int k = tid & 31, yq = tid >> 5;
        const float2 o0  = os[k];
        const float2 o32 = os[32*NM + k];
        const u64 o0x = pkdup(o0.x), o0y = pkdup(o0.y);
        const u64 p32x = pkdup(o32.x), p32y = pkdup(o32.y), n32y = pkdup(-o32.y);
        for (int g = yq; g < ngrp; g += 8) {
            int y0 = ybase + g*4;
            ulonglong2 C32 = __ldg((const ulonglong2*)&g_Fyc[32*HP + y0]);
            ulonglong2 S32 = __ldg((const ulonglong2*)&g_Fys[32*HP + y0]);
            u64 R01 = f2fma(p32x, C32.x, f2fma(n32y, S32.x, o0x));
            u64 R23 = f2fma(p32x, C32.y, f2fma(n32y, S32.y, o0x));
            u64 I01 = f2fma(p32y, C32.x, f2fma(p32x, S32.x, o0y));
            u64 I23 = f2fma(p32y, C32.y, f2fma(p32x, S32.y, o0y));
            #pragma unroll 4
            for (int m = 1; m <= 31; m++) {
                float2 Ps = os[m*NM + k];
                float2 Qs = os[(64 - m)*NM + k];
                ulonglong2 C = __ldg((const ulonglong2*)&g_Fyc[m*HP + y0]);
                ulonglong2 S = __ldg((const ulonglong2*)&g_Fys[m*HP + y0]);
                u64 px_ = pkdup(Ps.x), py_ = pkdup(Ps.y);
                u64 qx_ = pkdup(Qs.x), qy_ = pkdup(-Qs.y);
                R01 = f2fma(px_, C.x, f2fma(py_, S.x, R01));
                R23 = f2fma(px_, C.y, f2fma(py_, S.y, R23));
                I01 = f2fma(qx_, C.x, f2fma(qy_, S.x, I01));
                I23 = f2fma(qx_, C.y, f2fma(qy_, S.y, I23));
            }
            float2 r01 = up(R01), r23 = up(R23), i01 = up(I01), i23 = up(I23);
            int yl = g*4;
            Us[(yl+0)*NM + k] = make_float2(r01.x*INV_HP, i01.x*INV_HP);
            Us[(yl+1)*NM + k] = make_float2(r01.y*INV_HP, i01.y*INV_HP);
            Us[(yl+2)*NM + k] = make_float2(r23.x*INV_HP, i23.x*INV_HP);
            Us[(yl+3)*NM + k] = make_float2(r23.y*INV_HP, i23.y*INV_HP);
        }
    }
    __syncthreads();

    // ---- phase B
    const int xt = tid % 34, yq2 = tid / 34;
    const int x0 = xt * 4;
    for (int g = yq2; g < ngrp; g += 8) {
        int yl = g*4;
        u64 EO[4][4];
        float u0[4];
        #pragma unroll
        for (int j = 0; j < 4; j++) {
            u0[j] = Us[(yl + j)*NM].x;
            #pragma unroll
            for (int q = 0; q < 4; q++) EO[j][q] = 0ULL;
        }
        for (int k = 1; k < NM; k++) {
            const ulonglong2* fp = (const ulonglong2*)&g_Fx[k*HP + x0];
            ulonglong2 wA = __ldg(fp);
            ulonglong2 wB = __ldg(fp + 1);
            #pragma unroll
            for (int j = 0; j < 4; j++) {
                u64 u = *(const u64*)&Us[(yl + j)*NM + k];
                EO[j][0] = f2fma(u, wA.x, EO[j][0]);
                EO[j][1] = f2fma(u, wA.y, EO[j][1]);
                EO[j][2] = f2fma(u, wB.x, EO[j][2]);
                EO[j][3] = f2fma(u, wB.y, EO[j][3]);
            }
        }
        #pragma unroll
        for (int j = 0; j < 4; j++) {
            int y = ybase + yl + j;
            float2 eo[4] = {up(EO[j][0]), up(EO[j][1]), up(EO[j][2]), up(EO[j][3])};
            if (xt < 33) {
                int idx = bo*NP + y*HP + x0;
                float4 h = *(const float4*)&g_hbr[idx];
                float4 rv = make_float4(
                    h.x + (u0[j] + 2.f*(eo[0].x + eo[0].y))*INV_HP,
                    h.y + (u0[j] + 2.f*(eo[1].x + eo[1].y))*INV_HP,
                    h.z + (u0[j] + 2.f*(eo[2].x + eo[2].y))*INV_HP,
                    h.w + (u0[j] + 2.f*(eo[3].x + eo[3].y))*INV_HP);
                if (LAST) { if (y < H0) *(float4*)&out[bo*NPIX0 + y*W0 + x0] = rv; }
                else      *(float4*)&g_x[idx] = rv;
                #pragma unroll
                for (int q = 0; q < 4; q++) {
                    if (xt == 0 && q == 0) continue;
                    int xm = 264 - (x0 + q);
                    float hm = __ldg(&g_hbr[bo*NP + y*HP + xm]);
                    float vm = hm + (u0[j] + 2.f*(eo[q].x - eo[q].y))*INV_HP;
                    if (LAST) { if (y < H0 && xm < W0) out[bo*NPIX0 + y*W0 + xm] = vm; }
                    else      g_x[bo*NP + y*HP + xm] = vm;
                }
            } else {   // x = 132 self-mirror
                int idx = bo*NP + y*HP + 132;
                float hm = __ldg(&g_hbr[idx]);
                float vm = hm + (u0[j] + 2.f*(eo[0].x + eo[0].y))*INV_HP;
                if (LAST) { if (y < H0) out[bo*NPIX0 + y*W0 + 132] = vm; }
                else      g_x[idx] = vm;
            }
        }
    }
}

// ---------------- launch -----------------------------------------------------
extern "C" void kernel_launch(void* const* d_in, const int* in_sizes, int n_in,
                              void* d_out, int out_size)
{
    const float* x   = (const float*)d_in[0];
    const float* lw1 = (const float*)d_in[1];
    const float* lb1 = (const float*)d_in[2];
    const float* lw2 = (const float*)d_in[3];
    const float* lb2 = (const float*)d_in[4];
    const float* cw  = (const float*)d_in[5];
    const float* cb  = (const float*)d_in[6];
    const float* m1w = (const float*)d_in[7];
    const float* m1b = (const float*)d_in[8];
    const float* m2w = (const float*)d_in[9];
    const float* m2b = (const float*)d_in[10];
    const float* s1r = (const float*)d_in[11];
    const float* s1i = (const float*)d_in[12];
    const float* s2r = (const float*)d_in[13];
    const float* s2i = (const float*)d_in[14];
    float* out = (float*)d_out;

    float *px, *ph, *pwf, *pw3, *pbf;
    cudaGetSymbolAddress((void**)&px,  g_x);
    cudaGetSymbolAddress((void**)&ph,  g_hbr);
    cudaGetSymbolAddress((void**)&pwf, g_WfT);
    cudaGetSymbolAddress((void**)&pw3, g_W3T);
    cudaGetSymbolAddress((void**)&pbf, g_bf);

    const int LOCAL_SMEM = 20480 * 4;              // 81920 B
    const int DFTR_SMEM  = 17 * HP * 8;            // 35904 B
    const int DFTC_SMEM  = 17 * HP * 8;            // 35904 B
    const int CMIX_SMEM  = NB*NC*NM * 8;           // 65536 B
    const int INV_SMEM   = (2048 + 68*NM) * 8;     // 33792 B
    cudaFuncSetAttribute(k_local,      cudaFuncAttributeMaxDynamicSharedMemorySize, LOCAL_SMEM);
    cudaFuncSetAttribute(k_chanmix,    cudaFuncAttributeMaxDynamicSharedMemorySize, CMIX_SMEM);

    k_tables<<<132, 256>>>();
    k_wfuse<<<194, 256>>>(cw, cb, m1w, m1b, m2w);
    k_zero_pad<<<4160, 256>>>();
    k_lift<<<dim3(256, NB), 256>>>(x, lw1, lb1, lw2, lb2);

    for (int L = 0; L < 3; L++) {
        k_local<<<dim3(NP/64, NB), 128, LOCAL_SMEM>>>(
            px, ph, pwf + L*8192, pbf + L*128, pw3 + L*8192, m2b + L*64);
        k_dft_rows<<<dim3(NB*NC, 2), 264, DFTR_SMEM>>>();
        k_dft_cols<<<dim3(NB*NC, 2), 256, DFTC_SMEM>>>();
        k_chanmix<<<dim3(4, 64), 256, CMIX_SMEM>>>(s1r + L*SPW, s1i + L*SPW, s2r + L*SPW, s2i + L*SPW);
        if (L < 2) k_inv<false><<<dim3(NB*NC, 4), 272, INV_SMEM>>>(out);
        else       k_inv<true ><<<dim3(NB*NC, 4), 272, INV_SMEM>>>(out);
    }
}